// round 12
// baseline (speedup 1.0000x reference)
#include <cuda_runtime.h>
#include <cuda_fp16.h>
#include <math.h>
#include <stdint.h>

// ---------------- problem constants ----------------
#define BATCH   8
#define CH      256
#define HH      64
#define WW      64
#define HWSZ    (HH*WW)          // 4096
#define NTOK    (BATCH*HWSZ)     // 32768
#define HID     1024
#define NHEAD   8
#define HDIM    32
#define CP2     (CH/2)           // 128 channel pairs

// ---------------- scratch ----------------
__device__ __half  g_ts[NTOK*CH];        // sub transposed [tok][c]
__device__ __half  g_to[NTOK*CH];        // ori transposed [tok][c]
__device__ __half2 g_q [NTOK*CP2];       // [tok][c] rows (fp16)
__device__ __half2 g_k [NTOK*CP2];
__device__ __half2 g_v [NTOK*CP2];
__device__ __half2 g_x [NTOK*CP2];       // attention out, [tok][c]
__device__ float   g_xp[NTOK*CH];        // proj out fp32 (residual/LN in)
__device__ __half  g_ln[NTOK*CH];        // layernorm out
__device__ __half  g_h [NTOK*HID];       // mlp hidden
__device__ __half  g_wq [CH*CH];         // fp16 weights
__device__ __half  g_wkv[2*CH*CH];       // wk rows 0..255 | wv rows 256..511
__device__ __half  g_wp [CH*CH];
__device__ __half  g_w1 [HID*CH];
__device__ __half  g_w2 [CH*HID];

// ---------------- helpers ----------------
__device__ __forceinline__ uint32_t smem_u32(const void* p) {
    uint32_t a;
    asm("{ .reg .u64 t; cvta.to.shared.u64 t, %1; cvt.u32.u64 %0, t; }"
        : "=r"(a) : "l"(p));
    return a;
}
__device__ __forceinline__ void cp16(uint32_t s, const void* g) {
    asm volatile("cp.async.cg.shared.global [%0], [%1], 16;" :: "r"(s), "l"(g));
}
#define CP_COMMIT() asm volatile("cp.async.commit_group;" ::: "memory")
#define CP_WAIT1()  asm volatile("cp.async.wait_group 1;" ::: "memory")

__device__ __forceinline__ void ldsm_x4(uint32_t r[4], uint32_t addr) {
    asm volatile("ldmatrix.sync.aligned.m8n8.x4.shared.b16 {%0,%1,%2,%3}, [%4];"
        : "=r"(r[0]), "=r"(r[1]), "=r"(r[2]), "=r"(r[3]) : "r"(addr));
}
__device__ __forceinline__ void mma_f16(float c[4], const uint32_t a[4],
                                        uint32_t b0, uint32_t b1) {
    asm volatile(
        "mma.sync.aligned.m16n8k16.row.col.f32.f16.f16.f32 "
        "{%0,%1,%2,%3}, {%4,%5,%6,%7}, {%8,%9}, {%0,%1,%2,%3};\n"
        : "+f"(c[0]), "+f"(c[1]), "+f"(c[2]), "+f"(c[3])
        : "r"(a[0]), "r"(a[1]), "r"(a[2]), "r"(a[3]), "r"(b0), "r"(b1));
}

// =====================================================================
// fp16 NT GEMM: CTA 128x128, 256 threads (8 warps, warp 32x64),
// K-chunk 64, 3-stage cp.async, single __syncthreads per K-chunk.
// MODE 6: combined qkv. bx<2: q -> out1; bx>=2: n<256 -> aux (k),
//         else out2 (v). All plain fp16 [m][CH] row stores.
// MODE 0: proj -> +bias, fp32 store [m][CH]
// MODE 1: fc1  -> +bias, exact GELU, half store [m][HID]
// MODE 2: fc2  -> +bias +resid fp32 (aux), transposed fp32 store [B][C][H][W]
// =====================================================================
#define STAGE_B 32768   // 16KB A + 16KB B
#define SMEM_SZ (3*STAGE_B)

template<int MODE, int KDIM>
__global__ __launch_bounds__(256, 2)
void gemm_h(const __half* __restrict__ A, const __half* __restrict__ Wt,
            const float* __restrict__ bias, void* __restrict__ out1,
            void* __restrict__ aux,
            const __half* __restrict__ A2, const __half* __restrict__ W2,
            void* __restrict__ out2)
{
    extern __shared__ __align__(128) char smem[];
    const uint32_t sb = smem_u32(smem);

    const int tid  = threadIdx.x;
    const int lane = tid & 31;
    const int wid  = tid >> 5;
    const int wm   = wid & 3;
    const int wn   = wid >> 2;
    const int lq   = lane >> 2;
    const int lr   = lane & 3;

    const __half* Ap;
    const __half* Wp;
    int nT;
    bool isq = true;
    if (MODE == 6) {
        isq = (blockIdx.x < 2);
        if (isq) { Ap = A;  Wp = Wt; nT = blockIdx.x * 128; }
        else     { Ap = A2; Wp = W2; nT = (blockIdx.x - 2) * 128; }
    } else {
        Ap = A; Wp = Wt; nT = blockIdx.x * 128;
    }
    const int mT = blockIdx.y * 128;
    const int NCH = KDIM / 64;

    const int arow  = wm * 32 + (lane & 15);
    const int aqsel = lane >> 4;
    const uint32_t abase0 = (uint32_t)arow * 128;
    const uint32_t abase1 = (uint32_t)(arow + 16) * 128;
    const int axor = arow & 7;
    const int brow  = wn * 64 + (lane & 15);
    const int bqsel = lane >> 4;

    float acc[2][8][4];
    #pragma unroll
    for (int i = 0; i < 2; i++)
        #pragma unroll
        for (int j = 0; j < 8; j++)
            #pragma unroll
            for (int u = 0; u < 4; u++) acc[i][j][u] = 0.f;

    auto load_stage = [&](int s, int kt) {
        const uint32_t ab = sb + s * STAGE_B;
        const uint32_t bbm = ab + 16384;
        #pragma unroll
        for (int j = 0; j < 4; j++) {
            int c = tid + j * 256;
            int row = c >> 3, q = c & 7;
            uint32_t off = (uint32_t)row * 128 + (uint32_t)((q ^ (row & 7)) * 16);
            cp16(ab  + off, Ap + (size_t)(mT + row) * KDIM + kt + q * 8);
            cp16(bbm + off, Wp + (size_t)(nT + row) * KDIM + kt + q * 8);
        }
    };

    load_stage(0, 0);  CP_COMMIT();
    if (NCH > 1) load_stage(1, 64);
    CP_COMMIT();

    for (int it = 0; it < NCH; it++) {
        CP_WAIT1();
        __syncthreads();
        if (it + 2 < NCH) load_stage((it + 2) % 3, (it + 2) * 64);
        CP_COMMIT();

        const uint32_t ab = sb + (it % 3) * STAGE_B;
        const uint32_t bbm = ab + 16384;

        #pragma unroll
        for (int ks = 0; ks < 4; ks++) {
            const int q0 = ks * 2;
            uint32_t af[2][4];
            {
                const int qa = q0 + aqsel;
                ldsm_x4(af[0], ab + abase0 + (uint32_t)((qa ^ axor) * 16));
                ldsm_x4(af[1], ab + abase1 + (uint32_t)((qa ^ axor) * 16));
            }
            #pragma unroll
            for (int nt2 = 0; nt2 < 4; nt2++) {
                const int row = brow + nt2 * 16;
                const int qb = q0 + bqsel;
                uint32_t bf[4];
                ldsm_x4(bf, bbm + (uint32_t)row * 128 + (uint32_t)((qb ^ (row & 7)) * 16));
                mma_f16(acc[0][nt2*2  ], af[0], bf[0], bf[2]);
                mma_f16(acc[0][nt2*2+1], af[0], bf[1], bf[3]);
                mma_f16(acc[1][nt2*2  ], af[1], bf[0], bf[2]);
                mma_f16(acc[1][nt2*2+1], af[1], bf[1], bf[3]);
            }
        }
    }

    // ---------------- epilogue ----------------
    #pragma unroll
    for (int mt = 0; mt < 2; mt++) {
        #pragma unroll
        for (int idx = 0; idx < 8; idx++) {
            const int nt2 = idx >> 1, tt = idx & 1;
            const int m0 = mT + wm * 32 + mt * 16 + lq;
            const int n0 = nT + wn * 64 + nt2 * 16 + tt * 8 + (lr << 1);
            const float* cc = acc[mt][idx];

            if (MODE == 6) {
                // plain [m][CH] fp16 row store
                __half2* dst = isq ? (__half2*)out1
                                   : ((n0 < CH) ? (__half2*)aux : (__half2*)out2);
                const int ch2 = (n0 & (CH - 1)) >> 1;
                dst[(size_t)m0 * CP2 + ch2]       = __floats2half2_rn(cc[0], cc[1]);
                dst[(size_t)(m0 + 8) * CP2 + ch2] = __floats2half2_rn(cc[2], cc[3]);
            } else if (MODE == 0) {
                float* o = (float*)out1;
                float2 bv = *(const float2*)&bias[n0];
                *(float2*)&o[(size_t)m0 * CH + n0] =
                    make_float2(cc[0] + bv.x, cc[1] + bv.y);
                *(float2*)&o[(size_t)(m0 + 8) * CH + n0] =
                    make_float2(cc[2] + bv.x, cc[3] + bv.y);
            } else if (MODE == 1) {
                __half* o = (__half*)out1;
                float2 bv = *(const float2*)&bias[n0];
                float v[4] = {cc[0] + bv.x, cc[1] + bv.y, cc[2] + bv.x, cc[3] + bv.y};
                #pragma unroll
                for (int u = 0; u < 4; u++)
                    v[u] = 0.5f * v[u] * (1.f + erff(v[u] * 0.70710678118654752f));
                *(__half2*)&o[(size_t)m0 * HID + n0]       = __floats2half2_rn(v[0], v[1]);
                *(__half2*)&o[(size_t)(m0 + 8) * HID + n0] = __floats2half2_rn(v[2], v[3]);
            } else {
                float* o = (float*)out1;
                const float* resid = (const float*)aux;
                float2 bv = *(const float2*)&bias[n0];
                float2 r0 = *(const float2*)&resid[(size_t)m0 * CH + n0];
                float2 r1 = *(const float2*)&resid[(size_t)(m0 + 8) * CH + n0];
                const int bi = m0 >> 12;
                const int hw = m0 & 4095;
                float* p = o + (size_t)bi * CH * HWSZ;
                p[(size_t)(n0    ) * HWSZ + hw    ] = cc[0] + bv.x + r0.x;
                p[(size_t)(n0 + 1) * HWSZ + hw    ] = cc[1] + bv.y + r0.y;
                p[(size_t)(n0    ) * HWSZ + hw + 8] = cc[2] + bv.x + r1.x;
                p[(size_t)(n0 + 1) * HWSZ + hw + 8] = cc[3] + bv.y + r1.y;
            }
        }
    }
}

// =====================================================================
// Tiled transpose + fp16 cvt: [b][256][4096] fp32 -> [b*4096][256] fp16
// =====================================================================
__global__ void transpose_h(const float* __restrict__ in, __half* __restrict__ out)
{
    __shared__ float t[32][33];
    const int b  = blockIdx.z;
    const int p0 = blockIdx.x * 32;
    const int c0 = blockIdx.y * 32;
    const int tx = threadIdx.x, ty = threadIdx.y;   // 32 x 8
    const float* ib = in + (size_t)b * CH * HWSZ;
    __half* ob = out + (size_t)b * HWSZ * CH;
    #pragma unroll
    for (int i = 0; i < 4; i++)
        t[ty + 8*i][tx] = ib[(size_t)(c0 + ty + 8*i) * HWSZ + p0 + tx];
    __syncthreads();
    #pragma unroll
    for (int i = 0; i < 4; i++)
        ob[(size_t)(p0 + ty + 8*i) * CH + c0 + tx] = __float2half_rn(t[tx][ty + 8*i]);
}

// =====================================================================
// Dilated 3x3 local attention on [tok][256] fp16 rows.
// Per tap: one 64B contiguous head-slice (4 x float4). Branchless mask.
// 1 thread = (pixel, head). fp32 math.
// =====================================================================
__global__ __launch_bounds__(128)
void attn_kernel(const __half2* __restrict__ q,
                 const __half2* __restrict__ k,
                 const __half2* __restrict__ v,
                 __half2* __restrict__ xo)
{
    const int b    = blockIdx.z;
    const int head = blockIdx.y;
    const int n    = blockIdx.x * 128 + threadIdx.x;
    const int py   = n >> 6;
    const int px   = n & 63;
    const int dil  = (head >> 1) + 1;
    const int ho   = head * (HDIM / 2);          // half2 offset within row

    // q head-slice: 4 x float4 = 16 half2
    float2 qr[16];
    {
        const float4* qp = (const float4*)(q + (size_t)(b * HWSZ + n) * CP2 + ho);
        #pragma unroll
        for (int j = 0; j < 4; j++) {
            float4 r = qp[j];
            const __half2* h = (const __half2*)&r;
            qr[j*4+0] = __half22float2(h[0]);
            qr[j*4+1] = __half22float2(h[1]);
            qr[j*4+2] = __half22float2(h[2]);
            qr[j*4+3] = __half22float2(h[3]);
        }
    }

    int nn[9];
    float msk[9];
    #pragma unroll
    for (int t = 0; t < 9; t++) {
        int yy = py + (t / 3 - 1) * dil;
        int xx = px + (t % 3 - 1) * dil;
        const bool in = (yy >= 0 && yy < HH && xx >= 0 && xx < WW);
        nn[t] = in ? (yy * WW + xx) : n;
        msk[t] = in ? 1.f : 0.f;
    }

    float logit[9];
    #pragma unroll
    for (int t = 0; t < 9; t++) {
        const float4* kp = (const float4*)(k + (size_t)(b * HWSZ + nn[t]) * CP2 + ho);
        float acc = 0.f;
        #pragma unroll
        for (int j = 0; j < 4; j++) {
            float4 r = kp[j];
            const __half2* h = (const __half2*)&r;
            #pragma unroll
            for (int u = 0; u < 4; u++) {
                float2 kv = __half22float2(h[u]);
                acc += qr[j*4+u].x * kv.x + qr[j*4+u].y * kv.y;
            }
        }
        logit[t] = acc * msk[t] * 0.17677669529663687f;
    }

    float mx = logit[0];
    #pragma unroll
    for (int t = 1; t < 9; t++) mx = fmaxf(mx, logit[t]);
    float s = 0.f;
    #pragma unroll
    for (int t = 0; t < 9; t++) { logit[t] = __expf(logit[t] - mx); s += logit[t]; }
    const float inv = 1.f / s;
    #pragma unroll
    for (int t = 0; t < 9; t++) logit[t] *= inv * msk[t];

    float2 o[16];
    #pragma unroll
    for (int cp = 0; cp < 16; cp++) o[cp] = make_float2(0.f, 0.f);
    #pragma unroll
    for (int t = 0; t < 9; t++) {
        const float4* vp = (const float4*)(v + (size_t)(b * HWSZ + nn[t]) * CP2 + ho);
        const float w = logit[t];
        #pragma unroll
        for (int j = 0; j < 4; j++) {
            float4 r = vp[j];
            const __half2* h = (const __half2*)&r;
            #pragma unroll
            for (int u = 0; u < 4; u++) {
                float2 vv = __half22float2(h[u]);
                o[j*4+u].x += w * vv.x;
                o[j*4+u].y += w * vv.y;
            }
        }
    }

    float4* xp = (float4*)(xo + (size_t)(b * HWSZ + n) * CP2 + ho);
    #pragma unroll
    for (int j = 0; j < 4; j++) {
        float4 r;
        __half2* h = (__half2*)&r;
        #pragma unroll
        for (int u = 0; u < 4; u++)
            h[u] = __floats2half2_rn(o[j*4+u].x, o[j*4+u].y);
        xp[j] = r;
    }
}

// =====================================================================
// LayerNorm over 256 channels: fp32 in (g_xp), fp16 out (g_ln).
// =====================================================================
__global__ void ln_kernel(const float* __restrict__ xp,
                          const float* __restrict__ w,
                          const float* __restrict__ bb,
                          __half2* __restrict__ out)
{
    const int warp = threadIdx.x >> 5;
    const int lane = threadIdx.x & 31;
    const int tok  = blockIdx.x * 8 + warp;
    const float* row = xp + (size_t)tok * CH;

    float4 v0 = *(const float4*)&row[lane * 8];
    float4 v1 = *(const float4*)&row[lane * 8 + 4];
    float va[8] = {v0.x, v0.y, v0.z, v0.w, v1.x, v1.y, v1.z, v1.w};

    float s = 0.f, sq = 0.f;
    #pragma unroll
    for (int u = 0; u < 8; u++) { s += va[u]; sq += va[u] * va[u]; }
    #pragma unroll
    for (int o = 16; o; o >>= 1) {
        s  += __shfl_xor_sync(0xffffffffu, s,  o);
        sq += __shfl_xor_sync(0xffffffffu, sq, o);
    }
    const float mean = s * (1.f / 256.f);
    const float var  = sq * (1.f / 256.f) - mean * mean;
    const float inv  = rsqrtf(var + 1e-5f);

    __half2* orow = out + (size_t)tok * CP2 + lane * 4;
    #pragma unroll
    for (int j = 0; j < 4; j++) {
        int ch = lane * 8 + j * 2;
        float a0 = (va[j*2]   - mean) * inv * w[ch]     + bb[ch];
        float a1 = (va[j*2+1] - mean) * inv * w[ch + 1] + bb[ch + 1];
        orow[j] = __floats2half2_rn(a0, a1);
    }
}

// =====================================================================
// Fused weight conversion: all six weights in one launch.
// =====================================================================
__global__ void cvt_all(const float* __restrict__ wq, const float* __restrict__ wk,
                        const float* __restrict__ wv, const float* __restrict__ wp,
                        const float* __restrict__ w1, const float* __restrict__ w2,
                        __half* __restrict__ owq, __half* __restrict__ owkv,
                        __half* __restrict__ owp, __half* __restrict__ ow1,
                        __half* __restrict__ ow2)
{
    const int i = blockIdx.x * 256 + threadIdx.x;
    const int S = CH * CH;          // 65536
    if      (i <     S) owq [i        ] = __float2half_rn(wq[i]);
    else if (i < 2 * S) owkv[i - S    ] = __float2half_rn(wk[i - S]);
    else if (i < 3 * S) owkv[i - S    ] = __float2half_rn(wv[i - 2*S]);
    else if (i < 4 * S) owp [i - 3*S  ] = __float2half_rn(wp[i - 3*S]);
    else if (i < 8 * S) ow1 [i - 4*S  ] = __float2half_rn(w1[i - 4*S]);
    else                ow2 [i - 8*S  ] = __float2half_rn(w2[i - 8*S]);
}

// =====================================================================
extern "C" void kernel_launch(void* const* d_in, const int* in_sizes, int n_in,
                              void* d_out, int out_size)
{
    const float* sub    = (const float*)d_in[0];
    const float* ori    = (const float*)d_in[1];
    const float* wq     = (const float*)d_in[2];
    const float* wk     = (const float*)d_in[3];
    const float* wv     = (const float*)d_in[4];
    const float* proj_w = (const float*)d_in[5];
    const float* proj_b = (const float*)d_in[6];
    const float* ln_w   = (const float*)d_in[7];
    const float* ln_b   = (const float*)d_in[8];
    const float* fc1_w  = (const float*)d_in[9];
    const float* fc1_b  = (const float*)d_in[10];
    const float* fc2_w  = (const float*)d_in[11];
    const float* fc2_b  = (const float*)d_in[12];
    float* out = (float*)d_out;

    __half *p_ts, *p_to, *p_ln, *p_h, *p_wq, *p_wkv, *p_wp, *p_w1, *p_w2;
    __half2 *p_q, *p_k, *p_v, *p_x;
    float *p_xp;
    cudaGetSymbolAddress((void**)&p_ts,  g_ts);
    cudaGetSymbolAddress((void**)&p_to,  g_to);
    cudaGetSymbolAddress((void**)&p_q,   g_q);
    cudaGetSymbolAddress((void**)&p_k,   g_k);
    cudaGetSymbolAddress((void**)&p_v,   g_v);
    cudaGetSymbolAddress((void**)&p_x,   g_x);
    cudaGetSymbolAddress((void**)&p_xp,  g_xp);
    cudaGetSymbolAddress((void**)&p_ln,  g_ln);
    cudaGetSymbolAddress((void**)&p_h,   g_h);
    cudaGetSymbolAddress((void**)&p_wq,  g_wq);
    cudaGetSymbolAddress((void**)&p_wkv, g_wkv);
    cudaGetSymbolAddress((void**)&p_wp,  g_wp);
    cudaGetSymbolAddress((void**)&p_w1,  g_w1);
    cudaGetSymbolAddress((void**)&p_w2,  g_w2);

    cudaFuncSetAttribute(gemm_h<6, CH >, cudaFuncAttributeMaxDynamicSharedMemorySize, SMEM_SZ);
    cudaFuncSetAttribute(gemm_h<0, CH >, cudaFuncAttributeMaxDynamicSharedMemorySize, SMEM_SZ);
    cudaFuncSetAttribute(gemm_h<1, CH >, cudaFuncAttributeMaxDynamicSharedMemorySize, SMEM_SZ);
    cudaFuncSetAttribute(gemm_h<2, HID>, cudaFuncAttributeMaxDynamicSharedMemorySize, SMEM_SZ);

    // 0: all weight conversions
    cvt_all<<<(12 * CH * CH) / 256, 256>>>(wq, wk, wv, proj_w, fc1_w, fc2_w,
                                           p_wq, p_wkv, p_wp, p_w1, p_w2);

    // 1,2: transpose inputs to [tok][c] fp16
    dim3 gt(HWSZ / 32, CH / 32, BATCH);
    dim3 bt(32, 8);
    transpose_h<<<gt, bt>>>(sub, p_ts);
    transpose_h<<<gt, bt>>>(ori, p_to);

    // 3: combined q + kv GEMM (bx<2: q; bx>=2: k|v), [tok][CH] fp16 out
    dim3 gqkv(6, NTOK / 128);
    gemm_h<6, CH><<<gqkv, 256, SMEM_SZ>>>(p_ts, p_wq, nullptr, p_q, p_k,
                                          p_to, p_wkv, p_v);

    // 4: attention -> g_x [tok][c] fp16
    dim3 ga(HWSZ / 128, NHEAD, BATCH);
    attn_kernel<<<ga, 128>>>(p_q, p_k, p_v, p_x);

    // 5: proj + bias -> g_xp fp32
    dim3 gp(CH / 128, NTOK / 128);
    gemm_h<0, CH><<<gp, 256, SMEM_SZ>>>((const __half*)p_x, p_wp, proj_b, p_xp,
                                        nullptr, nullptr, nullptr, nullptr);

    // 6: layernorm -> g_ln fp16
    ln_kernel<<<NTOK / 8, 256>>>(p_xp, ln_w, ln_b, (__half2*)p_ln);

    // 7: fc1 + bias + GELU -> g_h fp16
    dim3 g1(HID / 128, NTOK / 128);
    gemm_h<1, CH><<<g1, 256, SMEM_SZ>>>(p_ln, p_w1, fc1_b, p_h,
                                        nullptr, nullptr, nullptr, nullptr);

    // 8: fc2 + bias + residual, transposed fp32 store -> d_out [B][C][H][W]
    dim3 g2(CH / 128, NTOK / 128);
    gemm_h<2, HID><<<g2, 256, SMEM_SZ>>>(p_h, p_w2, fc2_b, out, p_xp,
                                         nullptr, nullptr, nullptr);
}

// round 13
// speedup vs baseline: 1.1732x; 1.1732x over previous
#include <cuda_runtime.h>
#include <cuda_fp16.h>
#include <math.h>
#include <stdint.h>

// ---------------- problem constants ----------------
#define BATCH   8
#define CH      256
#define HH      64
#define WW      64
#define HWSZ    (HH*WW)          // 4096
#define NTOK    (BATCH*HWSZ)     // 32768
#define HID     1024
#define NHEAD   8
#define HDIM    32
#define CP2     (CH/2)           // 128 channel pairs

// ---------------- scratch ----------------
__device__ __half  g_ts[NTOK*CH];        // sub transposed [tok][c]
__device__ __half  g_to[NTOK*CH];        // ori transposed [tok][c]
__device__ __half2 g_q [BATCH*CP2*HWSZ]; // channel-pair-major
__device__ __half2 g_k [BATCH*CP2*HWSZ];
__device__ __half2 g_v [BATCH*CP2*HWSZ];
__device__ __half2 g_x [NTOK*CP2];       // attention out, [tok][c] pairs
__device__ float   g_xp[NTOK*CH];        // proj out fp32 (residual/LN in)
__device__ __half  g_ln[NTOK*CH];        // layernorm out
__device__ __half  g_h [NTOK*HID];       // mlp hidden
__device__ __half  g_wq [CH*CH];         // fp16 weights
__device__ __half  g_wkv[2*CH*CH];       // wk rows 0..255 | wv rows 256..511
__device__ __half  g_wp [CH*CH];
__device__ __half  g_w1 [HID*CH];
__device__ __half  g_w2 [CH*HID];

// ---------------- helpers ----------------
__device__ __forceinline__ uint32_t smem_u32(const void* p) {
    uint32_t a;
    asm("{ .reg .u64 t; cvta.to.shared.u64 t, %1; cvt.u32.u64 %0, t; }"
        : "=r"(a) : "l"(p));
    return a;
}
__device__ __forceinline__ void cp16(uint32_t s, const void* g) {
    asm volatile("cp.async.cg.shared.global [%0], [%1], 16;" :: "r"(s), "l"(g));
}
#define CP_COMMIT() asm volatile("cp.async.commit_group;" ::: "memory")
#define CP_WAIT1()  asm volatile("cp.async.wait_group 1;" ::: "memory")

__device__ __forceinline__ void ldsm_x4(uint32_t r[4], uint32_t addr) {
    asm volatile("ldmatrix.sync.aligned.m8n8.x4.shared.b16 {%0,%1,%2,%3}, [%4];"
        : "=r"(r[0]), "=r"(r[1]), "=r"(r[2]), "=r"(r[3]) : "r"(addr));
}
__device__ __forceinline__ void mma_f16(float c[4], const uint32_t a[4],
                                        uint32_t b0, uint32_t b1) {
    asm volatile(
        "mma.sync.aligned.m16n8k16.row.col.f32.f16.f16.f32 "
        "{%0,%1,%2,%3}, {%4,%5,%6,%7}, {%8,%9}, {%0,%1,%2,%3};\n"
        : "+f"(c[0]), "+f"(c[1]), "+f"(c[2]), "+f"(c[3])
        : "r"(a[0]), "r"(a[1]), "r"(a[2]), "r"(a[3]), "r"(b0), "r"(b1));
}

// =====================================================================
// fp16 NT GEMM: CTA 128x128, 256 threads (8 warps, warp 32x64),
// K-chunk 64, 3-stage cp.async, SINGLE __syncthreads per K-chunk.
// MODE 6: combined qkv. bx<2: q -> out1; bx>=2: n<256 -> aux (k),
//         else out2 (v). Channel-pair-major transposed stores.
// MODE 0: proj -> +bias, fp32 store [m][CH]
// MODE 1: fc1  -> +bias, exact GELU, half store [m][HID]
// MODE 2: fc2  -> +bias +resid fp32 (aux), transposed fp32 store [B][C][H][W]
// =====================================================================
#define STAGE_B 32768   // 16KB A + 16KB B
#define SMEM_SZ (3*STAGE_B)

template<int MODE, int KDIM>
__global__ __launch_bounds__(256, 2)
void gemm_h(const __half* __restrict__ A, const __half* __restrict__ Wt,
            const float* __restrict__ bias, void* __restrict__ out1,
            void* __restrict__ aux,
            const __half* __restrict__ A2, const __half* __restrict__ W2,
            void* __restrict__ out2)
{
    extern __shared__ __align__(128) char smem[];
    const uint32_t sb = smem_u32(smem);

    const int tid  = threadIdx.x;
    const int lane = tid & 31;
    const int wid  = tid >> 5;
    const int wm   = wid & 3;
    const int wn   = wid >> 2;
    const int lq   = lane >> 2;
    const int lr   = lane & 3;

    const __half* Ap;
    const __half* Wp;
    int nT;
    bool isq = true;
    if (MODE == 6) {
        isq = (blockIdx.x < 2);
        if (isq) { Ap = A;  Wp = Wt; nT = blockIdx.x * 128; }
        else     { Ap = A2; Wp = W2; nT = (blockIdx.x - 2) * 128; }
    } else {
        Ap = A; Wp = Wt; nT = blockIdx.x * 128;
    }
    const int mT = blockIdx.y * 128;
    const int NCH = KDIM / 64;

    const int arow  = wm * 32 + (lane & 15);
    const int aqsel = lane >> 4;
    const uint32_t abase0 = (uint32_t)arow * 128;
    const uint32_t abase1 = (uint32_t)(arow + 16) * 128;
    const int axor = arow & 7;
    const int brow  = wn * 64 + (lane & 15);
    const int bqsel = lane >> 4;

    float acc[2][8][4];
    #pragma unroll
    for (int i = 0; i < 2; i++)
        #pragma unroll
        for (int j = 0; j < 8; j++)
            #pragma unroll
            for (int u = 0; u < 4; u++) acc[i][j][u] = 0.f;

    auto load_stage = [&](int s, int kt) {
        const uint32_t ab = sb + s * STAGE_B;
        const uint32_t bbm = ab + 16384;
        #pragma unroll
        for (int j = 0; j < 4; j++) {
            int c = tid + j * 256;
            int row = c >> 3, q = c & 7;
            uint32_t off = (uint32_t)row * 128 + (uint32_t)((q ^ (row & 7)) * 16);
            cp16(ab  + off, Ap + (size_t)(mT + row) * KDIM + kt + q * 8);
            cp16(bbm + off, Wp + (size_t)(nT + row) * KDIM + kt + q * 8);
        }
    };

    load_stage(0, 0);  CP_COMMIT();
    if (NCH > 1) load_stage(1, 64);
    CP_COMMIT();

    for (int it = 0; it < NCH; it++) {
        CP_WAIT1();            // chunk it arrived (this thread's groups)
        __syncthreads();       // publish chunk it; all warps done with it-1
        if (it + 2 < NCH) load_stage((it + 2) % 3, (it + 2) * 64);
        CP_COMMIT();           // keep one group per iteration

        const uint32_t ab = sb + (it % 3) * STAGE_B;
        const uint32_t bbm = ab + 16384;

        #pragma unroll
        for (int ks = 0; ks < 4; ks++) {
            const int q0 = ks * 2;
            uint32_t af[2][4];
            {
                const int qa = q0 + aqsel;
                ldsm_x4(af[0], ab + abase0 + (uint32_t)((qa ^ axor) * 16));
                ldsm_x4(af[1], ab + abase1 + (uint32_t)((qa ^ axor) * 16));
            }
            #pragma unroll
            for (int nt2 = 0; nt2 < 4; nt2++) {
                const int row = brow + nt2 * 16;
                const int qb = q0 + bqsel;
                uint32_t bf[4];
                ldsm_x4(bf, bbm + (uint32_t)row * 128 + (uint32_t)((qb ^ (row & 7)) * 16));
                mma_f16(acc[0][nt2*2  ], af[0], bf[0], bf[2]);
                mma_f16(acc[0][nt2*2+1], af[0], bf[1], bf[3]);
                mma_f16(acc[1][nt2*2  ], af[1], bf[0], bf[2]);
                mma_f16(acc[1][nt2*2+1], af[1], bf[1], bf[3]);
            }
        }
    }

    // ---------------- epilogue ----------------
    #pragma unroll
    for (int mt = 0; mt < 2; mt++) {
        #pragma unroll
        for (int idx = 0; idx < 8; idx++) {
            const int nt2 = idx >> 1, tt = idx & 1;
            const int m0 = mT + wm * 32 + mt * 16 + lq;
            const int n0 = nT + wn * 64 + nt2 * 16 + tt * 8 + (lr << 1);
            const float* cc = acc[mt][idx];

            if (MODE == 6) {
                const int bi = m0 >> 12;
                const int hw = m0 & 4095;
                __half2* dst = isq ? (__half2*)out1
                                   : ((n0 < CH) ? (__half2*)aux : (__half2*)out2);
                const int ch = n0 & (CH - 1);
                __half2* p = dst + (size_t)bi * CP2 * HWSZ + (size_t)(ch >> 1) * HWSZ;
                p[hw    ] = __floats2half2_rn(cc[0], cc[1]);
                p[hw + 8] = __floats2half2_rn(cc[2], cc[3]);
            } else if (MODE == 0) {
                float* o = (float*)out1;
                float2 bv = *(const float2*)&bias[n0];
                *(float2*)&o[(size_t)m0 * CH + n0] =
                    make_float2(cc[0] + bv.x, cc[1] + bv.y);
                *(float2*)&o[(size_t)(m0 + 8) * CH + n0] =
                    make_float2(cc[2] + bv.x, cc[3] + bv.y);
            } else if (MODE == 1) {
                __half* o = (__half*)out1;
                float2 bv = *(const float2*)&bias[n0];
                float v[4] = {cc[0] + bv.x, cc[1] + bv.y, cc[2] + bv.x, cc[3] + bv.y};
                #pragma unroll
                for (int u = 0; u < 4; u++)
                    v[u] = 0.5f * v[u] * (1.f + erff(v[u] * 0.70710678118654752f));
                *(__half2*)&o[(size_t)m0 * HID + n0]       = __floats2half2_rn(v[0], v[1]);
                *(__half2*)&o[(size_t)(m0 + 8) * HID + n0] = __floats2half2_rn(v[2], v[3]);
            } else {
                float* o = (float*)out1;
                const float* resid = (const float*)aux;
                float2 bv = *(const float2*)&bias[n0];
                float2 r0 = *(const float2*)&resid[(size_t)m0 * CH + n0];
                float2 r1 = *(const float2*)&resid[(size_t)(m0 + 8) * CH + n0];
                const int bi = m0 >> 12;
                const int hw = m0 & 4095;
                float* p = o + (size_t)bi * CH * HWSZ;
                p[(size_t)(n0    ) * HWSZ + hw    ] = cc[0] + bv.x + r0.x;
                p[(size_t)(n0 + 1) * HWSZ + hw    ] = cc[1] + bv.y + r0.y;
                p[(size_t)(n0    ) * HWSZ + hw + 8] = cc[2] + bv.x + r1.x;
                p[(size_t)(n0 + 1) * HWSZ + hw + 8] = cc[3] + bv.y + r1.y;
            }
        }
    }
}

// =====================================================================
// Combined tiled transpose + fp16 cvt for BOTH inputs in one launch.
// z < 8: sub -> g_ts (batch z); z >= 8: ori -> g_to (batch z-8).
// =====================================================================
__global__ void transpose_h2(const float* __restrict__ sub, const float* __restrict__ ori,
                             __half* __restrict__ ts, __half* __restrict__ to)
{
    __shared__ float t[32][33];
    const int z  = blockIdx.z;
    const int b  = z & 7;
    const float* in = (z < 8) ? sub : ori;
    __half* out     = (z < 8) ? ts  : to;
    const int p0 = blockIdx.x * 32;
    const int c0 = blockIdx.y * 32;
    const int tx = threadIdx.x, ty = threadIdx.y;   // 32 x 8
    const float* ib = in + (size_t)b * CH * HWSZ;
    __half* ob = out + (size_t)b * HWSZ * CH;
    #pragma unroll
    for (int i = 0; i < 4; i++)
        t[ty + 8*i][tx] = ib[(size_t)(c0 + ty + 8*i) * HWSZ + p0 + tx];
    __syncthreads();
    #pragma unroll
    for (int i = 0; i < 4; i++)
        ob[(size_t)(p0 + ty + 8*i) * CH + c0 + tx] = __float2half_rn(t[tx][ty + 8*i]);
}

// =====================================================================
// Dilated 3x3 local attention (proven): branchless gathers,
// channel-pair-major q/k/v, fp32 math. 1 thread = (pixel, head).
// =====================================================================
__global__ __launch_bounds__(128)
void attn_kernel(const __half2* __restrict__ q,
                 const __half2* __restrict__ k,
                 const __half2* __restrict__ v,
                 __half2* __restrict__ xo)
{
    const int b    = blockIdx.z;
    const int head = blockIdx.y;
    const int n    = blockIdx.x * 128 + threadIdx.x;
    const int py   = n >> 6;
    const int px   = n & 63;
    const int dil  = (head >> 1) + 1;

    const size_t base = ((size_t)b * CP2 + head * (HDIM/2)) * HWSZ;
    const __half2* qb = q + base + n;
    const __half2* kb = k + base;
    const __half2* vb = v + base;

    float2 qr[16];
    #pragma unroll
    for (int cp = 0; cp < 16; cp++) qr[cp] = __half22float2(qb[(size_t)cp * HWSZ]);

    int nn[9];
    float msk[9];
    #pragma unroll
    for (int t = 0; t < 9; t++) {
        int yy = py + (t / 3 - 1) * dil;
        int xx = px + (t % 3 - 1) * dil;
        const bool in = (yy >= 0 && yy < HH && xx >= 0 && xx < WW);
        nn[t] = in ? (yy * WW + xx) : n;
        msk[t] = in ? 1.f : 0.f;
    }

    float logit[9];
    #pragma unroll
    for (int t = 0; t < 9; t++) {
        float acc = 0.f;
        #pragma unroll
        for (int cp = 0; cp < 16; cp++) {
            float2 kv = __half22float2(kb[(size_t)cp * HWSZ + nn[t]]);
            acc += qr[cp].x * kv.x + qr[cp].y * kv.y;
        }
        logit[t] = acc * msk[t] * 0.17677669529663687f;
    }

    float mx = logit[0];
    #pragma unroll
    for (int t = 1; t < 9; t++) mx = fmaxf(mx, logit[t]);
    float s = 0.f;
    #pragma unroll
    for (int t = 0; t < 9; t++) { logit[t] = __expf(logit[t] - mx); s += logit[t]; }
    const float inv = 1.f / s;
    #pragma unroll
    for (int t = 0; t < 9; t++) logit[t] *= inv * msk[t];

    __half2* xrow = xo + (size_t)(b * HWSZ + n) * CP2 + head * (HDIM/2);
    #pragma unroll
    for (int cp = 0; cp < 16; cp++) {
        float ox = 0.f, oy = 0.f;
        #pragma unroll
        for (int t = 0; t < 9; t++) {
            float2 vv = __half22float2(vb[(size_t)cp * HWSZ + nn[t]]);
            ox += logit[t] * vv.x;
            oy += logit[t] * vv.y;
        }
        xrow[cp] = __floats2half2_rn(ox, oy);
    }
}

// =====================================================================
// LayerNorm over 256 channels: fp32 in (g_xp), fp16 out (g_ln).
// =====================================================================
__global__ void ln_kernel(const float* __restrict__ xp,
                          const float* __restrict__ w,
                          const float* __restrict__ bb,
                          __half2* __restrict__ out)
{
    const int warp = threadIdx.x >> 5;
    const int lane = threadIdx.x & 31;
    const int tok  = blockIdx.x * 8 + warp;
    const float* row = xp + (size_t)tok * CH;

    float4 v0 = *(const float4*)&row[lane * 8];
    float4 v1 = *(const float4*)&row[lane * 8 + 4];
    float va[8] = {v0.x, v0.y, v0.z, v0.w, v1.x, v1.y, v1.z, v1.w};

    float s = 0.f, sq = 0.f;
    #pragma unroll
    for (int u = 0; u < 8; u++) { s += va[u]; sq += va[u] * va[u]; }
    #pragma unroll
    for (int o = 16; o; o >>= 1) {
        s  += __shfl_xor_sync(0xffffffffu, s,  o);
        sq += __shfl_xor_sync(0xffffffffu, sq, o);
    }
    const float mean = s * (1.f / 256.f);
    const float var  = sq * (1.f / 256.f) - mean * mean;
    const float inv  = rsqrtf(var + 1e-5f);

    __half2* orow = out + (size_t)tok * CP2 + lane * 4;
    #pragma unroll
    for (int j = 0; j < 4; j++) {
        int ch = lane * 8 + j * 2;
        float a0 = (va[j*2]   - mean) * inv * w[ch]     + bb[ch];
        float a1 = (va[j*2+1] - mean) * inv * w[ch + 1] + bb[ch + 1];
        orow[j] = __floats2half2_rn(a0, a1);
    }
}

// =====================================================================
// Fused weight conversion: all six weights in one launch.
// =====================================================================
__global__ void cvt_all(const float* __restrict__ wq, const float* __restrict__ wk,
                        const float* __restrict__ wv, const float* __restrict__ wp,
                        const float* __restrict__ w1, const float* __restrict__ w2,
                        __half* __restrict__ owq, __half* __restrict__ owkv,
                        __half* __restrict__ owp, __half* __restrict__ ow1,
                        __half* __restrict__ ow2)
{
    const int i = blockIdx.x * 256 + threadIdx.x;
    const int S = CH * CH;          // 65536
    if      (i <     S) owq [i        ] = __float2half_rn(wq[i]);
    else if (i < 2 * S) owkv[i - S    ] = __float2half_rn(wk[i - S]);
    else if (i < 3 * S) owkv[i - S    ] = __float2half_rn(wv[i - 2*S]);
    else if (i < 4 * S) owp [i - 3*S  ] = __float2half_rn(wp[i - 3*S]);
    else if (i < 8 * S) ow1 [i - 4*S  ] = __float2half_rn(w1[i - 4*S]);
    else                ow2 [i - 8*S  ] = __float2half_rn(w2[i - 8*S]);
}

// =====================================================================
extern "C" void kernel_launch(void* const* d_in, const int* in_sizes, int n_in,
                              void* d_out, int out_size)
{
    const float* sub    = (const float*)d_in[0];
    const float* ori    = (const float*)d_in[1];
    const float* wq     = (const float*)d_in[2];
    const float* wk     = (const float*)d_in[3];
    const float* wv     = (const float*)d_in[4];
    const float* proj_w = (const float*)d_in[5];
    const float* proj_b = (const float*)d_in[6];
    const float* ln_w   = (const float*)d_in[7];
    const float* ln_b   = (const float*)d_in[8];
    const float* fc1_w  = (const float*)d_in[9];
    const float* fc1_b  = (const float*)d_in[10];
    const float* fc2_w  = (const float*)d_in[11];
    const float* fc2_b  = (const float*)d_in[12];
    float* out = (float*)d_out;

    __half *p_ts, *p_to, *p_ln, *p_h, *p_wq, *p_wkv, *p_wp, *p_w1, *p_w2;
    __half2 *p_q, *p_k, *p_v, *p_x;
    float *p_xp;
    cudaGetSymbolAddress((void**)&p_ts,  g_ts);
    cudaGetSymbolAddress((void**)&p_to,  g_to);
    cudaGetSymbolAddress((void**)&p_q,   g_q);
    cudaGetSymbolAddress((void**)&p_k,   g_k);
    cudaGetSymbolAddress((void**)&p_v,   g_v);
    cudaGetSymbolAddress((void**)&p_x,   g_x);
    cudaGetSymbolAddress((void**)&p_xp,  g_xp);
    cudaGetSymbolAddress((void**)&p_ln,  g_ln);
    cudaGetSymbolAddress((void**)&p_h,   g_h);
    cudaGetSymbolAddress((void**)&p_wq,  g_wq);
    cudaGetSymbolAddress((void**)&p_wkv, g_wkv);
    cudaGetSymbolAddress((void**)&p_wp,  g_wp);
    cudaGetSymbolAddress((void**)&p_w1,  g_w1);
    cudaGetSymbolAddress((void**)&p_w2,  g_w2);

    cudaFuncSetAttribute(gemm_h<6, CH >, cudaFuncAttributeMaxDynamicSharedMemorySize, SMEM_SZ);
    cudaFuncSetAttribute(gemm_h<0, CH >, cudaFuncAttributeMaxDynamicSharedMemorySize, SMEM_SZ);
    cudaFuncSetAttribute(gemm_h<1, CH >, cudaFuncAttributeMaxDynamicSharedMemorySize, SMEM_SZ);
    cudaFuncSetAttribute(gemm_h<2, HID>, cudaFuncAttributeMaxDynamicSharedMemorySize, SMEM_SZ);

    // 0: all weight conversions
    cvt_all<<<(12 * CH * CH) / 256, 256>>>(wq, wk, wv, proj_w, fc1_w, fc2_w,
                                           p_wq, p_wkv, p_wp, p_w1, p_w2);

    // 1: both transposes in one launch
    dim3 gt(HWSZ / 32, CH / 32, 2 * BATCH);
    dim3 bt(32, 8);
    transpose_h2<<<gt, bt>>>(sub, ori, p_ts, p_to);

    // 2: combined q + kv GEMM (bx<2: q; bx>=2: k|v), channel-pair-major out
    dim3 gqkv(6, NTOK / 128);
    gemm_h<6, CH><<<gqkv, 256, SMEM_SZ>>>(p_ts, p_wq, nullptr, p_q, p_k,
                                          p_to, p_wkv, p_v);

    // 3: attention -> g_x [tok][c] fp16
    dim3 ga(HWSZ / 128, NHEAD, BATCH);
    attn_kernel<<<ga, 128>>>(p_q, p_k, p_v, p_x);

    // 4: proj + bias -> g_xp fp32
    dim3 gp(CH / 128, NTOK / 128);
    gemm_h<0, CH><<<gp, 256, SMEM_SZ>>>((const __half*)p_x, p_wp, proj_b, p_xp,
                                        nullptr, nullptr, nullptr, nullptr);

    // 5: layernorm -> g_ln fp16
    ln_kernel<<<NTOK / 8, 256>>>(p_xp, ln_w, ln_b, (__half2*)p_ln);

    // 6: fc1 + bias + GELU -> g_h fp16
    dim3 g1(HID / 128, NTOK / 128);
    gemm_h<1, CH><<<g1, 256, SMEM_SZ>>>(p_ln, p_w1, fc1_b, p_h,
                                        nullptr, nullptr, nullptr, nullptr);

    // 7: fc2 + bias + residual, transposed fp32 store -> d_out [B][C][H][W]
    dim3 g2(CH / 128, NTOK / 128);
    gemm_h<2, HID><<<g2, 256, SMEM_SZ>>>(p_h, p_w2, fc2_b, out, p_xp,
                                         nullptr, nullptr, nullptr);
}

// round 14
// speedup vs baseline: 1.2533x; 1.0682x over previous
#include <cuda_runtime.h>
#include <cuda_fp16.h>
#include <math.h>
#include <stdint.h>

// ---------------- problem constants ----------------
#define BATCH   8
#define CH      256
#define HH      64
#define WW      64
#define HWSZ    (HH*WW)          // 4096
#define NTOK    (BATCH*HWSZ)     // 32768
#define HID     1024
#define NHEAD   8
#define HDIM    32
#define CP2     (CH/2)           // 128 channel pairs
#define NGRP    32               // channel groups of 8 halves (16B)

// ---------------- scratch ----------------
__device__ __half  g_ts[NTOK*CH];        // sub transposed [tok][c]
__device__ __half  g_to[NTOK*CH];        // ori transposed [tok][c]
// q/k/v grouped layout: [b][grp(32)][hw][8 halves] = float4 per (grp,hw)
__device__ __half2 g_q [BATCH*NGRP*HWSZ*4];
__device__ __half2 g_k [BATCH*NGRP*HWSZ*4];
__device__ __half2 g_v [BATCH*NGRP*HWSZ*4];
__device__ __half2 g_x [NTOK*CP2];       // attention out, [tok][c] rows
__device__ float   g_xp[NTOK*CH];        // proj out fp32 (residual/LN in)
__device__ __half  g_ln[NTOK*CH];        // layernorm out
__device__ __half  g_h [NTOK*HID];       // mlp hidden
__device__ __half  g_wq [CH*CH];         // fp16 weights
__device__ __half  g_wkv[2*CH*CH];       // wk rows 0..255 | wv rows 256..511
__device__ __half  g_wp [CH*CH];
__device__ __half  g_w1 [HID*CH];
__device__ __half  g_w2 [CH*HID];

// ---------------- helpers ----------------
__device__ __forceinline__ uint32_t smem_u32(const void* p) {
    uint32_t a;
    asm("{ .reg .u64 t; cvta.to.shared.u64 t, %1; cvt.u32.u64 %0, t; }"
        : "=r"(a) : "l"(p));
    return a;
}
__device__ __forceinline__ void cp16(uint32_t s, const void* g) {
    asm volatile("cp.async.cg.shared.global [%0], [%1], 16;" :: "r"(s), "l"(g));
}
#define CP_COMMIT() asm volatile("cp.async.commit_group;" ::: "memory")
#define CP_WAIT1()  asm volatile("cp.async.wait_group 1;" ::: "memory")

__device__ __forceinline__ void ldsm_x4(uint32_t r[4], uint32_t addr) {
    asm volatile("ldmatrix.sync.aligned.m8n8.x4.shared.b16 {%0,%1,%2,%3}, [%4];"
        : "=r"(r[0]), "=r"(r[1]), "=r"(r[2]), "=r"(r[3]) : "r"(addr));
}
__device__ __forceinline__ void mma_f16(float c[4], const uint32_t a[4],
                                        uint32_t b0, uint32_t b1) {
    asm volatile(
        "mma.sync.aligned.m16n8k16.row.col.f32.f16.f16.f32 "
        "{%0,%1,%2,%3}, {%4,%5,%6,%7}, {%8,%9}, {%0,%1,%2,%3};\n"
        : "+f"(c[0]), "+f"(c[1]), "+f"(c[2]), "+f"(c[3])
        : "r"(a[0]), "r"(a[1]), "r"(a[2]), "r"(a[3]), "r"(b0), "r"(b1));
}

// =====================================================================
// fp16 NT GEMM: CTA 128x128, 256 threads (8 warps, warp 32x64),
// K-chunk 64, 3-stage cp.async, SINGLE __syncthreads per K-chunk.
// MODE 6: combined qkv. bx<2: q -> out1; bx>=2: n<256 -> aux (k),
//         else out2 (v). Grouped-channel stores [b][grp][hw][8].
// MODE 0: proj -> +bias, fp32 store [m][CH]
// MODE 1: fc1  -> +bias, exact GELU, half store [m][HID]
// MODE 2: fc2  -> +bias +resid fp32 (aux), transposed fp32 store [B][C][H][W]
// =====================================================================
#define STAGE_B 32768   // 16KB A + 16KB B
#define SMEM_SZ (3*STAGE_B)

template<int MODE, int KDIM>
__global__ __launch_bounds__(256, 2)
void gemm_h(const __half* __restrict__ A, const __half* __restrict__ Wt,
            const float* __restrict__ bias, void* __restrict__ out1,
            void* __restrict__ aux,
            const __half* __restrict__ A2, const __half* __restrict__ W2,
            void* __restrict__ out2)
{
    extern __shared__ __align__(128) char smem[];
    const uint32_t sb = smem_u32(smem);

    const int tid  = threadIdx.x;
    const int lane = tid & 31;
    const int wid  = tid >> 5;
    const int wm   = wid & 3;
    const int wn   = wid >> 2;
    const int lq   = lane >> 2;
    const int lr   = lane & 3;

    const __half* Ap;
    const __half* Wp;
    int nT;
    bool isq = true;
    if (MODE == 6) {
        isq = (blockIdx.x < 2);
        if (isq) { Ap = A;  Wp = Wt; nT = blockIdx.x * 128; }
        else     { Ap = A2; Wp = W2; nT = (blockIdx.x - 2) * 128; }
    } else {
        Ap = A; Wp = Wt; nT = blockIdx.x * 128;
    }
    const int mT = blockIdx.y * 128;
    const int NCH = KDIM / 64;

    const int arow  = wm * 32 + (lane & 15);
    const int aqsel = lane >> 4;
    const uint32_t abase0 = (uint32_t)arow * 128;
    const uint32_t abase1 = (uint32_t)(arow + 16) * 128;
    const int axor = arow & 7;
    const int brow  = wn * 64 + (lane & 15);
    const int bqsel = lane >> 4;

    float acc[2][8][4];
    #pragma unroll
    for (int i = 0; i < 2; i++)
        #pragma unroll
        for (int j = 0; j < 8; j++)
            #pragma unroll
            for (int u = 0; u < 4; u++) acc[i][j][u] = 0.f;

    auto load_stage = [&](int s, int kt) {
        const uint32_t ab = sb + s * STAGE_B;
        const uint32_t bbm = ab + 16384;
        #pragma unroll
        for (int j = 0; j < 4; j++) {
            int c = tid + j * 256;
            int row = c >> 3, q = c & 7;
            uint32_t off = (uint32_t)row * 128 + (uint32_t)((q ^ (row & 7)) * 16);
            cp16(ab  + off, Ap + (size_t)(mT + row) * KDIM + kt + q * 8);
            cp16(bbm + off, Wp + (size_t)(nT + row) * KDIM + kt + q * 8);
        }
    };

    load_stage(0, 0);  CP_COMMIT();
    if (NCH > 1) load_stage(1, 64);
    CP_COMMIT();

    for (int it = 0; it < NCH; it++) {
        CP_WAIT1();
        __syncthreads();
        if (it + 2 < NCH) load_stage((it + 2) % 3, (it + 2) * 64);
        CP_COMMIT();

        const uint32_t ab = sb + (it % 3) * STAGE_B;
        const uint32_t bbm = ab + 16384;

        #pragma unroll
        for (int ks = 0; ks < 4; ks++) {
            const int q0 = ks * 2;
            uint32_t af[2][4];
            {
                const int qa = q0 + aqsel;
                ldsm_x4(af[0], ab + abase0 + (uint32_t)((qa ^ axor) * 16));
                ldsm_x4(af[1], ab + abase1 + (uint32_t)((qa ^ axor) * 16));
            }
            #pragma unroll
            for (int nt2 = 0; nt2 < 4; nt2++) {
                const int row = brow + nt2 * 16;
                const int qb = q0 + bqsel;
                uint32_t bf[4];
                ldsm_x4(bf, bbm + (uint32_t)row * 128 + (uint32_t)((qb ^ (row & 7)) * 16));
                mma_f16(acc[0][nt2*2  ], af[0], bf[0], bf[2]);
                mma_f16(acc[0][nt2*2+1], af[0], bf[1], bf[3]);
                mma_f16(acc[1][nt2*2  ], af[1], bf[0], bf[2]);
                mma_f16(acc[1][nt2*2+1], af[1], bf[1], bf[3]);
            }
        }
    }

    // ---------------- epilogue ----------------
    #pragma unroll
    for (int mt = 0; mt < 2; mt++) {
        #pragma unroll
        for (int idx = 0; idx < 8; idx++) {
            const int nt2 = idx >> 1, tt = idx & 1;
            const int m0 = mT + wm * 32 + mt * 16 + lq;
            const int n0 = nT + wn * 64 + nt2 * 16 + tt * 8 + (lr << 1);
            const float* cc = acc[mt][idx];

            if (MODE == 6) {
                const int bi = m0 >> 12;
                const int hw = m0 & 4095;
                __half2* dst = isq ? (__half2*)out1
                                   : ((n0 < CH) ? (__half2*)aux : (__half2*)out2);
                const int ch  = n0 & (CH - 1);
                const int grp = ch >> 3;
                const int wi  = (ch & 7) >> 1;
                __half2* p = dst + ((((size_t)bi * NGRP + grp) * HWSZ + hw) << 2) + wi;
                p[0]  = __floats2half2_rn(cc[0], cc[1]);
                p[32] = __floats2half2_rn(cc[2], cc[3]);   // hw+8 -> +8*4 half2
            } else if (MODE == 0) {
                float* o = (float*)out1;
                float2 bv = *(const float2*)&bias[n0];
                *(float2*)&o[(size_t)m0 * CH + n0] =
                    make_float2(cc[0] + bv.x, cc[1] + bv.y);
                *(float2*)&o[(size_t)(m0 + 8) * CH + n0] =
                    make_float2(cc[2] + bv.x, cc[3] + bv.y);
            } else if (MODE == 1) {
                __half* o = (__half*)out1;
                float2 bv = *(const float2*)&bias[n0];
                float v[4] = {cc[0] + bv.x, cc[1] + bv.y, cc[2] + bv.x, cc[3] + bv.y};
                #pragma unroll
                for (int u = 0; u < 4; u++)
                    v[u] = 0.5f * v[u] * (1.f + erff(v[u] * 0.70710678118654752f));
                *(__half2*)&o[(size_t)m0 * HID + n0]       = __floats2half2_rn(v[0], v[1]);
                *(__half2*)&o[(size_t)(m0 + 8) * HID + n0] = __floats2half2_rn(v[2], v[3]);
            } else {
                float* o = (float*)out1;
                const float* resid = (const float*)aux;
                float2 bv = *(const float2*)&bias[n0];
                float2 r0 = *(const float2*)&resid[(size_t)m0 * CH + n0];
                float2 r1 = *(const float2*)&resid[(size_t)(m0 + 8) * CH + n0];
                const int bi = m0 >> 12;
                const int hw = m0 & 4095;
                float* p = o + (size_t)bi * CH * HWSZ;
                p[(size_t)(n0    ) * HWSZ + hw    ] = cc[0] + bv.x + r0.x;
                p[(size_t)(n0 + 1) * HWSZ + hw    ] = cc[1] + bv.y + r0.y;
                p[(size_t)(n0    ) * HWSZ + hw + 8] = cc[2] + bv.x + r1.x;
                p[(size_t)(n0 + 1) * HWSZ + hw + 8] = cc[3] + bv.y + r1.y;
            }
        }
    }
}

// =====================================================================
// Combined tiled transpose + fp16 cvt for BOTH inputs in one launch.
// =====================================================================
__global__ void transpose_h2(const float* __restrict__ sub, const float* __restrict__ ori,
                             __half* __restrict__ ts, __half* __restrict__ to)
{
    __shared__ float t[32][33];
    const int z  = blockIdx.z;
    const int b  = z & 7;
    const float* in = (z < 8) ? sub : ori;
    __half* out     = (z < 8) ? ts  : to;
    const int p0 = blockIdx.x * 32;
    const int c0 = blockIdx.y * 32;
    const int tx = threadIdx.x, ty = threadIdx.y;   // 32 x 8
    const float* ib = in + (size_t)b * CH * HWSZ;
    __half* ob = out + (size_t)b * HWSZ * CH;
    #pragma unroll
    for (int i = 0; i < 4; i++)
        t[ty + 8*i][tx] = ib[(size_t)(c0 + ty + 8*i) * HWSZ + p0 + tx];
    __syncthreads();
    #pragma unroll
    for (int i = 0; i < 4; i++)
        ob[(size_t)(p0 + ty + 8*i) * CH + c0 + tx] = __float2half_rn(t[tx][ty + 8*i]);
}

// =====================================================================
// Dilated 3x3 local attention on GROUPED q/k/v: per tap, 4 float4 loads
// (16B lane stride -> 4x128B coalesced warp sectors). Branchless mask.
// 1 thread = (pixel, head). fp32 math. x out: [tok][256] rows.
// =====================================================================
__global__ __launch_bounds__(128)
void attn_kernel(const float4* __restrict__ qf,
                 const float4* __restrict__ kf,
                 const float4* __restrict__ vf,
                 __half2* __restrict__ xo)
{
    const int b    = blockIdx.z;
    const int head = blockIdx.y;
    const int n    = blockIdx.x * 128 + threadIdx.x;
    const int py   = n >> 6;
    const int px   = n & 63;
    const int dil  = (head >> 1) + 1;

    const size_t gbase = ((size_t)b * NGRP + head * 4) * HWSZ;

    float2 qr[16];
    #pragma unroll
    for (int g = 0; g < 4; g++) {
        float4 r = qf[gbase + (size_t)g * HWSZ + n];
        const __half2* h = (const __half2*)&r;
        qr[g*4+0] = __half22float2(h[0]);
        qr[g*4+1] = __half22float2(h[1]);
        qr[g*4+2] = __half22float2(h[2]);
        qr[g*4+3] = __half22float2(h[3]);
    }

    int nn[9];
    float msk[9];
    #pragma unroll
    for (int t = 0; t < 9; t++) {
        int yy = py + (t / 3 - 1) * dil;
        int xx = px + (t % 3 - 1) * dil;
        const bool in = (yy >= 0 && yy < HH && xx >= 0 && xx < WW);
        nn[t] = in ? (yy * WW + xx) : n;
        msk[t] = in ? 1.f : 0.f;
    }

    float logit[9];
    #pragma unroll
    for (int t = 0; t < 9; t++) {
        float acc = 0.f;
        #pragma unroll
        for (int g = 0; g < 4; g++) {
            float4 r = kf[gbase + (size_t)g * HWSZ + nn[t]];
            const __half2* h = (const __half2*)&r;
            #pragma unroll
            for (int u = 0; u < 4; u++) {
                float2 kv = __half22float2(h[u]);
                acc += qr[g*4+u].x * kv.x + qr[g*4+u].y * kv.y;
            }
        }
        logit[t] = acc * msk[t] * 0.17677669529663687f;
    }

    float mx = logit[0];
    #pragma unroll
    for (int t = 1; t < 9; t++) mx = fmaxf(mx, logit[t]);
    float s = 0.f;
    #pragma unroll
    for (int t = 0; t < 9; t++) { logit[t] = __expf(logit[t] - mx); s += logit[t]; }
    const float inv = 1.f / s;
    #pragma unroll
    for (int t = 0; t < 9; t++) logit[t] *= inv * msk[t];

    float2 o[16];
    #pragma unroll
    for (int cp = 0; cp < 16; cp++) o[cp] = make_float2(0.f, 0.f);
    #pragma unroll
    for (int t = 0; t < 9; t++) {
        const float w = logit[t];
        #pragma unroll
        for (int g = 0; g < 4; g++) {
            float4 r = vf[gbase + (size_t)g * HWSZ + nn[t]];
            const __half2* h = (const __half2*)&r;
            #pragma unroll
            for (int u = 0; u < 4; u++) {
                float2 vv = __half22float2(h[u]);
                o[g*4+u].x += w * vv.x;
                o[g*4+u].y += w * vv.y;
            }
        }
    }

    // x out: contiguous [tok][256] row (feeds proj GEMM)
    float4* xp = (float4*)(xo + (size_t)(b * HWSZ + n) * CP2 + head * (HDIM/2));
    #pragma unroll
    for (int g = 0; g < 4; g++) {
        float4 r;
        __half2* h = (__half2*)&r;
        #pragma unroll
        for (int u = 0; u < 4; u++)
            h[u] = __floats2half2_rn(o[g*4+u].x, o[g*4+u].y);
        xp[g] = r;
    }
}

// =====================================================================
// LayerNorm over 256 channels: fp32 in (g_xp), fp16 out (g_ln).
// =====================================================================
__global__ void ln_kernel(const float* __restrict__ xp,
                          const float* __restrict__ w,
                          const float* __restrict__ bb,
                          __half2* __restrict__ out)
{
    const int warp = threadIdx.x >> 5;
    const int lane = threadIdx.x & 31;
    const int tok  = blockIdx.x * 8 + warp;
    const float* row = xp + (size_t)tok * CH;

    float4 v0 = *(const float4*)&row[lane * 8];
    float4 v1 = *(const float4*)&row[lane * 8 + 4];
    float va[8] = {v0.x, v0.y, v0.z, v0.w, v1.x, v1.y, v1.z, v1.w};

    float s = 0.f, sq = 0.f;
    #pragma unroll
    for (int u = 0; u < 8; u++) { s += va[u]; sq += va[u] * va[u]; }
    #pragma unroll
    for (int o = 16; o; o >>= 1) {
        s  += __shfl_xor_sync(0xffffffffu, s,  o);
        sq += __shfl_xor_sync(0xffffffffu, sq, o);
    }
    const float mean = s * (1.f / 256.f);
    const float var  = sq * (1.f / 256.f) - mean * mean;
    const float inv  = rsqrtf(var + 1e-5f);

    __half2* orow = out + (size_t)tok * CP2 + lane * 4;
    #pragma unroll
    for (int j = 0; j < 4; j++) {
        int ch = lane * 8 + j * 2;
        float a0 = (va[j*2]   - mean) * inv * w[ch]     + bb[ch];
        float a1 = (va[j*2+1] - mean) * inv * w[ch + 1] + bb[ch + 1];
        orow[j] = __floats2half2_rn(a0, a1);
    }
}

// =====================================================================
// Fused weight conversion: all six weights in one launch.
// =====================================================================
__global__ void cvt_all(const float* __restrict__ wq, const float* __restrict__ wk,
                        const float* __restrict__ wv, const float* __restrict__ wp,
                        const float* __restrict__ w1, const float* __restrict__ w2,
                        __half* __restrict__ owq, __half* __restrict__ owkv,
                        __half* __restrict__ owp, __half* __restrict__ ow1,
                        __half* __restrict__ ow2)
{
    const int i = blockIdx.x * 256 + threadIdx.x;
    const int S = CH * CH;          // 65536
    if      (i <     S) owq [i        ] = __float2half_rn(wq[i]);
    else if (i < 2 * S) owkv[i - S    ] = __float2half_rn(wk[i - S]);
    else if (i < 3 * S) owkv[i - S    ] = __float2half_rn(wv[i - 2*S]);
    else if (i < 4 * S) owp [i - 3*S  ] = __float2half_rn(wp[i - 3*S]);
    else if (i < 8 * S) ow1 [i - 4*S  ] = __float2half_rn(w1[i - 4*S]);
    else                ow2 [i - 8*S  ] = __float2half_rn(w2[i - 8*S]);
}

// =====================================================================
extern "C" void kernel_launch(void* const* d_in, const int* in_sizes, int n_in,
                              void* d_out, int out_size)
{
    const float* sub    = (const float*)d_in[0];
    const float* ori    = (const float*)d_in[1];
    const float* wq     = (const float*)d_in[2];
    const float* wk     = (const float*)d_in[3];
    const float* wv     = (const float*)d_in[4];
    const float* proj_w = (const float*)d_in[5];
    const float* proj_b = (const float*)d_in[6];
    const float* ln_w   = (const float*)d_in[7];
    const float* ln_b   = (const float*)d_in[8];
    const float* fc1_w  = (const float*)d_in[9];
    const float* fc1_b  = (const float*)d_in[10];
    const float* fc2_w  = (const float*)d_in[11];
    const float* fc2_b  = (const float*)d_in[12];
    float* out = (float*)d_out;

    __half *p_ts, *p_to, *p_ln, *p_h, *p_wq, *p_wkv, *p_wp, *p_w1, *p_w2;
    __half2 *p_q, *p_k, *p_v, *p_x;
    float *p_xp;
    cudaGetSymbolAddress((void**)&p_ts,  g_ts);
    cudaGetSymbolAddress((void**)&p_to,  g_to);
    cudaGetSymbolAddress((void**)&p_q,   g_q);
    cudaGetSymbolAddress((void**)&p_k,   g_k);
    cudaGetSymbolAddress((void**)&p_v,   g_v);
    cudaGetSymbolAddress((void**)&p_x,   g_x);
    cudaGetSymbolAddress((void**)&p_xp,  g_xp);
    cudaGetSymbolAddress((void**)&p_ln,  g_ln);
    cudaGetSymbolAddress((void**)&p_h,   g_h);
    cudaGetSymbolAddress((void**)&p_wq,  g_wq);
    cudaGetSymbolAddress((void**)&p_wkv, g_wkv);
    cudaGetSymbolAddress((void**)&p_wp,  g_wp);
    cudaGetSymbolAddress((void**)&p_w1,  g_w1);
    cudaGetSymbolAddress((void**)&p_w2,  g_w2);

    cudaFuncSetAttribute(gemm_h<6, CH >, cudaFuncAttributeMaxDynamicSharedMemorySize, SMEM_SZ);
    cudaFuncSetAttribute(gemm_h<0, CH >, cudaFuncAttributeMaxDynamicSharedMemorySize, SMEM_SZ);
    cudaFuncSetAttribute(gemm_h<1, CH >, cudaFuncAttributeMaxDynamicSharedMemorySize, SMEM_SZ);
    cudaFuncSetAttribute(gemm_h<2, HID>, cudaFuncAttributeMaxDynamicSharedMemorySize, SMEM_SZ);

    // 0: all weight conversions
    cvt_all<<<(12 * CH * CH) / 256, 256>>>(wq, wk, wv, proj_w, fc1_w, fc2_w,
                                           p_wq, p_wkv, p_wp, p_w1, p_w2);

    // 1: both transposes in one launch
    dim3 gt(HWSZ / 32, CH / 32, 2 * BATCH);
    dim3 bt(32, 8);
    transpose_h2<<<gt, bt>>>(sub, ori, p_ts, p_to);

    // 2: combined q + kv GEMM (bx<2: q; bx>=2: k|v), grouped-channel out
    dim3 gqkv(6, NTOK / 128);
    gemm_h<6, CH><<<gqkv, 256, SMEM_SZ>>>(p_ts, p_wq, nullptr, p_q, p_k,
                                          p_to, p_wkv, p_v);

    // 3: attention -> g_x [tok][256] fp16
    dim3 ga(HWSZ / 128, NHEAD, BATCH);
    attn_kernel<<<ga, 128>>>((const float4*)p_q, (const float4*)p_k,
                             (const float4*)p_v, p_x);

    // 4: proj + bias -> g_xp fp32
    dim3 gp(CH / 128, NTOK / 128);
    gemm_h<0, CH><<<gp, 256, SMEM_SZ>>>((const __half*)p_x, p_wp, proj_b, p_xp,
                                        nullptr, nullptr, nullptr, nullptr);

    // 5: layernorm -> g_ln fp16
    ln_kernel<<<NTOK / 8, 256>>>(p_xp, ln_w, ln_b, (__half2*)p_ln);

    // 6: fc1 + bias + GELU -> g_h fp16
    dim3 g1(HID / 128, NTOK / 128);
    gemm_h<1, CH><<<g1, 256, SMEM_SZ>>>(p_ln, p_w1, fc1_b, p_h,
                                        nullptr, nullptr, nullptr, nullptr);

    // 7: fc2 + bias + residual, transposed fp32 store -> d_out [B][C][H][W]
    dim3 g2(CH / 128, NTOK / 128);
    gemm_h<2, HID><<<g2, 256, SMEM_SZ>>>(p_h, p_w2, fc2_b, out, p_xp,
                                         nullptr, nullptr, nullptr);
}

// round 15
// speedup vs baseline: 1.2738x; 1.0164x over previous
#include <cuda_runtime.h>
#include <cuda_fp16.h>
#include <math.h>
#include <stdint.h>

// ---------------- problem constants ----------------
#define BATCH   8
#define CH      256
#define HH      64
#define WW      64
#define HWSZ    (HH*WW)          // 4096
#define NTOK    (BATCH*HWSZ)     // 32768
#define HID     1024
#define NHEAD   8
#define HDIM    32
#define CP2     (CH/2)           // 128 channel pairs
#define NGRP    32               // channel groups of 8 halves (16B)

// ---------------- scratch ----------------
__device__ __half  g_ts[NTOK*CH];        // sub transposed [tok][c]
__device__ __half  g_to[NTOK*CH];        // ori transposed [tok][c]
// q/k/v grouped layout: [b][grp(32)][hw][8 halves] = float4 per (grp,hw)
__device__ __half2 g_q [BATCH*NGRP*HWSZ*4];
__device__ __half2 g_k [BATCH*NGRP*HWSZ*4];
__device__ __half2 g_v [BATCH*NGRP*HWSZ*4];
__device__ __half2 g_x [NTOK*CP2];       // attention out, [tok][c] rows
__device__ float   g_xp[NTOK*CH];        // proj out fp32 (residual/LN in)
__device__ __half  g_ln[NTOK*CH];        // layernorm out
__device__ __half  g_h [NTOK*HID];       // mlp hidden
__device__ __half  g_wq [CH*CH];         // fp16 weights
__device__ __half  g_wkv[2*CH*CH];       // wk rows 0..255 | wv rows 256..511
__device__ __half  g_wp [CH*CH];
__device__ __half  g_w1 [HID*CH];
__device__ __half  g_w2 [CH*HID];

// ---------------- helpers ----------------
__device__ __forceinline__ uint32_t smem_u32(const void* p) {
    uint32_t a;
    asm("{ .reg .u64 t; cvta.to.shared.u64 t, %1; cvt.u32.u64 %0, t; }"
        : "=r"(a) : "l"(p));
    return a;
}
__device__ __forceinline__ void cp16(uint32_t s, const void* g) {
    asm volatile("cp.async.cg.shared.global [%0], [%1], 16;" :: "r"(s), "l"(g));
}
#define CP_COMMIT() asm volatile("cp.async.commit_group;" ::: "memory")
#define CP_WAIT1()  asm volatile("cp.async.wait_group 1;" ::: "memory")

__device__ __forceinline__ void ldsm_x4(uint32_t r[4], uint32_t addr) {
    asm volatile("ldmatrix.sync.aligned.m8n8.x4.shared.b16 {%0,%1,%2,%3}, [%4];"
        : "=r"(r[0]), "=r"(r[1]), "=r"(r[2]), "=r"(r[3]) : "r"(addr));
}
__device__ __forceinline__ void mma_f16(float c[4], const uint32_t a[4],
                                        uint32_t b0, uint32_t b1) {
    asm volatile(
        "mma.sync.aligned.m16n8k16.row.col.f32.f16.f16.f32 "
        "{%0,%1,%2,%3}, {%4,%5,%6,%7}, {%8,%9}, {%0,%1,%2,%3};\n"
        : "+f"(c[0]), "+f"(c[1]), "+f"(c[2]), "+f"(c[3])
        : "r"(a[0]), "r"(a[1]), "r"(a[2]), "r"(a[3]), "r"(b0), "r"(b1));
}

// =====================================================================
// fp16 NT GEMM: CTA 128x128, 256 threads (8 warps, warp 32x64),
// K-chunk 64, 3-stage cp.async, SINGLE __syncthreads per K-chunk.
// MODE 6: combined qkv. bx<2: q -> out1; bx>=2: n<256 -> aux (k),
//         else out2 (v). Grouped-channel stores [b][grp][hw][8].
// MODE 0: proj -> +bias, fp32 store [m][CH]
// MODE 1: fc1  -> +bias, exact GELU, half store [m][HID]
// MODE 2: fc2  -> +bias +resid fp32 (aux), transposed fp32 store [B][C][H][W]
// =====================================================================
#define STAGE_B 32768   // 16KB A + 16KB B
#define SMEM_SZ (3*STAGE_B)

template<int MODE, int KDIM>
__global__ __launch_bounds__(256, 2)
void gemm_h(const __half* __restrict__ A, const __half* __restrict__ Wt,
            const float* __restrict__ bias, void* __restrict__ out1,
            void* __restrict__ aux,
            const __half* __restrict__ A2, const __half* __restrict__ W2,
            void* __restrict__ out2)
{
    extern __shared__ __align__(128) char smem[];
    const uint32_t sb = smem_u32(smem);

    const int tid  = threadIdx.x;
    const int lane = tid & 31;
    const int wid  = tid >> 5;
    const int wm   = wid & 3;
    const int wn   = wid >> 2;
    const int lq   = lane >> 2;
    const int lr   = lane & 3;

    const __half* Ap;
    const __half* Wp;
    int nT;
    bool isq = true;
    if (MODE == 6) {
        isq = (blockIdx.x < 2);
        if (isq) { Ap = A;  Wp = Wt; nT = blockIdx.x * 128; }
        else     { Ap = A2; Wp = W2; nT = (blockIdx.x - 2) * 128; }
    } else {
        Ap = A; Wp = Wt; nT = blockIdx.x * 128;
    }
    const int mT = blockIdx.y * 128;
    const int NCH = KDIM / 64;

    const int arow  = wm * 32 + (lane & 15);
    const int aqsel = lane >> 4;
    const uint32_t abase0 = (uint32_t)arow * 128;
    const uint32_t abase1 = (uint32_t)(arow + 16) * 128;
    const int axor = arow & 7;
    const int brow  = wn * 64 + (lane & 15);
    const int bqsel = lane >> 4;

    float acc[2][8][4];
    #pragma unroll
    for (int i = 0; i < 2; i++)
        #pragma unroll
        for (int j = 0; j < 8; j++)
            #pragma unroll
            for (int u = 0; u < 4; u++) acc[i][j][u] = 0.f;

    auto load_stage = [&](int s, int kt) {
        const uint32_t ab = sb + s * STAGE_B;
        const uint32_t bbm = ab + 16384;
        #pragma unroll
        for (int j = 0; j < 4; j++) {
            int c = tid + j * 256;
            int row = c >> 3, q = c & 7;
            uint32_t off = (uint32_t)row * 128 + (uint32_t)((q ^ (row & 7)) * 16);
            cp16(ab  + off, Ap + (size_t)(mT + row) * KDIM + kt + q * 8);
            cp16(bbm + off, Wp + (size_t)(nT + row) * KDIM + kt + q * 8);
        }
    };

    load_stage(0, 0);  CP_COMMIT();
    if (NCH > 1) load_stage(1, 64);
    CP_COMMIT();

    for (int it = 0; it < NCH; it++) {
        CP_WAIT1();
        __syncthreads();
        if (it + 2 < NCH) load_stage((it + 2) % 3, (it + 2) * 64);
        CP_COMMIT();

        const uint32_t ab = sb + (it % 3) * STAGE_B;
        const uint32_t bbm = ab + 16384;

        #pragma unroll
        for (int ks = 0; ks < 4; ks++) {
            const int q0 = ks * 2;
            uint32_t af[2][4];
            {
                const int qa = q0 + aqsel;
                ldsm_x4(af[0], ab + abase0 + (uint32_t)((qa ^ axor) * 16));
                ldsm_x4(af[1], ab + abase1 + (uint32_t)((qa ^ axor) * 16));
            }
            #pragma unroll
            for (int nt2 = 0; nt2 < 4; nt2++) {
                const int row = brow + nt2 * 16;
                const int qb = q0 + bqsel;
                uint32_t bf[4];
                ldsm_x4(bf, bbm + (uint32_t)row * 128 + (uint32_t)((qb ^ (row & 7)) * 16));
                mma_f16(acc[0][nt2*2  ], af[0], bf[0], bf[2]);
                mma_f16(acc[0][nt2*2+1], af[0], bf[1], bf[3]);
                mma_f16(acc[1][nt2*2  ], af[1], bf[0], bf[2]);
                mma_f16(acc[1][nt2*2+1], af[1], bf[1], bf[3]);
            }
        }
    }

    // ---------------- epilogue ----------------
    #pragma unroll
    for (int mt = 0; mt < 2; mt++) {
        #pragma unroll
        for (int idx = 0; idx < 8; idx++) {
            const int nt2 = idx >> 1, tt = idx & 1;
            const int m0 = mT + wm * 32 + mt * 16 + lq;
            const int n0 = nT + wn * 64 + nt2 * 16 + tt * 8 + (lr << 1);
            const float* cc = acc[mt][idx];

            if (MODE == 6) {
                const int bi = m0 >> 12;
                const int hw = m0 & 4095;
                __half2* dst = isq ? (__half2*)out1
                                   : ((n0 < CH) ? (__half2*)aux : (__half2*)out2);
                const int ch  = n0 & (CH - 1);
                const int grp = ch >> 3;
                const int wi  = (ch & 7) >> 1;
                __half2* p = dst + ((((size_t)bi * NGRP + grp) * HWSZ + hw) << 2) + wi;
                p[0]  = __floats2half2_rn(cc[0], cc[1]);
                p[32] = __floats2half2_rn(cc[2], cc[3]);
            } else if (MODE == 0) {
                float* o = (float*)out1;
                float2 bv = *(const float2*)&bias[n0];
                *(float2*)&o[(size_t)m0 * CH + n0] =
                    make_float2(cc[0] + bv.x, cc[1] + bv.y);
                *(float2*)&o[(size_t)(m0 + 8) * CH + n0] =
                    make_float2(cc[2] + bv.x, cc[3] + bv.y);
            } else if (MODE == 1) {
                __half* o = (__half*)out1;
                float2 bv = *(const float2*)&bias[n0];
                float v[4] = {cc[0] + bv.x, cc[1] + bv.y, cc[2] + bv.x, cc[3] + bv.y};
                #pragma unroll
                for (int u = 0; u < 4; u++)
                    v[u] = 0.5f * v[u] * (1.f + erff(v[u] * 0.70710678118654752f));
                *(__half2*)&o[(size_t)m0 * HID + n0]       = __floats2half2_rn(v[0], v[1]);
                *(__half2*)&o[(size_t)(m0 + 8) * HID + n0] = __floats2half2_rn(v[2], v[3]);
            } else {
                float* o = (float*)out1;
                const float* resid = (const float*)aux;
                float2 bv = *(const float2*)&bias[n0];
                float2 r0 = *(const float2*)&resid[(size_t)m0 * CH + n0];
                float2 r1 = *(const float2*)&resid[(size_t)(m0 + 8) * CH + n0];
                const int bi = m0 >> 12;
                const int hw = m0 & 4095;
                float* p = o + (size_t)bi * CH * HWSZ;
                p[(size_t)(n0    ) * HWSZ + hw    ] = cc[0] + bv.x + r0.x;
                p[(size_t)(n0 + 1) * HWSZ + hw    ] = cc[1] + bv.y + r0.y;
                p[(size_t)(n0    ) * HWSZ + hw + 8] = cc[2] + bv.x + r1.x;
                p[(size_t)(n0 + 1) * HWSZ + hw + 8] = cc[3] + bv.y + r1.y;
            }
        }
    }
}

// =====================================================================
// Fused prologue: z 0..15 -> transpose (+fp16 cvt) of sub/ori;
//                 z 16..18 -> weight fp32->fp16 conversions.
// Block (32, 8) = 256 threads.
// =====================================================================
__global__ void prep_all(const float* __restrict__ sub, const float* __restrict__ ori,
                         __half* __restrict__ ts, __half* __restrict__ to,
                         const float* __restrict__ wq, const float* __restrict__ wk,
                         const float* __restrict__ wv, const float* __restrict__ wp,
                         const float* __restrict__ w1, const float* __restrict__ w2,
                         __half* __restrict__ owq, __half* __restrict__ owkv,
                         __half* __restrict__ owp, __half* __restrict__ ow1,
                         __half* __restrict__ ow2)
{
    const int z = blockIdx.z;
    if (z < 16) {
        __shared__ float t[32][33];
        const int b  = z & 7;
        const float* in = (z < 8) ? sub : ori;
        __half* out     = (z < 8) ? ts  : to;
        const int p0 = blockIdx.x * 32;
        const int c0 = blockIdx.y * 32;
        const int tx = threadIdx.x, ty = threadIdx.y;
        const float* ib = in + (size_t)b * CH * HWSZ;
        __half* ob = out + (size_t)b * HWSZ * CH;
        #pragma unroll
        for (int i = 0; i < 4; i++)
            t[ty + 8*i][tx] = ib[(size_t)(c0 + ty + 8*i) * HWSZ + p0 + tx];
        __syncthreads();
        #pragma unroll
        for (int i = 0; i < 4; i++)
            ob[(size_t)(p0 + ty + 8*i) * CH + c0 + tx] = __float2half_rn(t[tx][ty + 8*i]);
    } else {
        const int tid = threadIdx.y * 32 + threadIdx.x;
        const int slot = ((z - 16) * gridDim.y + blockIdx.y) * gridDim.x + blockIdx.x;
        const int i = slot * 256 + tid;
        const int S = CH * CH;          // 65536
        if (i >= 12 * S) return;
        if      (i <     S) owq [i      ] = __float2half_rn(wq[i]);
        else if (i < 2 * S) owkv[i - S  ] = __float2half_rn(wk[i - S]);
        else if (i < 3 * S) owkv[i - S  ] = __float2half_rn(wv[i - 2*S]);
        else if (i < 4 * S) owp [i - 3*S] = __float2half_rn(wp[i - 3*S]);
        else if (i < 8 * S) ow1 [i - 4*S] = __float2half_rn(w1[i - 4*S]);
        else                ow2 [i - 8*S] = __float2half_rn(w2[i - 8*S]);
    }
}

// =====================================================================
// Dilated 3x3 local attention, grouped q/k/v, HFMA2 logits.
// Per tap: 4 coalesced float4 loads; q·k via 16 hfma2 into 4 half2
// accumulators (chain 4), reduced in fp32. v path stays fp32.
// =====================================================================
__global__ __launch_bounds__(128)
void attn_kernel(const float4* __restrict__ qf,
                 const float4* __restrict__ kf,
                 const float4* __restrict__ vf,
                 __half2* __restrict__ xo)
{
    const int b    = blockIdx.z;
    const int head = blockIdx.y;
    const int n    = blockIdx.x * 128 + threadIdx.x;
    const int py   = n >> 6;
    const int px   = n & 63;
    const int dil  = (head >> 1) + 1;

    const size_t gbase = ((size_t)b * NGRP + head * 4) * HWSZ;

    // q kept as raw half2 (16 regs)
    __half2 qh[16];
    #pragma unroll
    for (int g = 0; g < 4; g++) {
        float4 r = qf[gbase + (size_t)g * HWSZ + n];
        const __half2* h = (const __half2*)&r;
        qh[g*4+0] = h[0]; qh[g*4+1] = h[1]; qh[g*4+2] = h[2]; qh[g*4+3] = h[3];
    }

    int nn[9];
    float msk[9];
    #pragma unroll
    for (int t = 0; t < 9; t++) {
        int yy = py + (t / 3 - 1) * dil;
        int xx = px + (t % 3 - 1) * dil;
        const bool in = (yy >= 0 && yy < HH && xx >= 0 && xx < WW);
        nn[t] = in ? (yy * WW + xx) : n;
        msk[t] = in ? 1.f : 0.f;
    }

    const __half2 hz = __floats2half2_rn(0.f, 0.f);
    float logit[9];
    #pragma unroll
    for (int t = 0; t < 9; t++) {
        __half2 pa[4] = {hz, hz, hz, hz};
        #pragma unroll
        for (int g = 0; g < 4; g++) {
            float4 r = kf[gbase + (size_t)g * HWSZ + nn[t]];
            const __half2* h = (const __half2*)&r;
            #pragma unroll
            for (int u = 0; u < 4; u++)
                pa[u] = __hfma2(qh[g*4+u], h[u], pa[u]);
        }
        float2 f0 = __half22float2(pa[0]);
        float2 f1 = __half22float2(pa[1]);
        float2 f2 = __half22float2(pa[2]);
        float2 f3 = __half22float2(pa[3]);
        float acc = (f0.x + f0.y) + (f1.x + f1.y) + (f2.x + f2.y) + (f3.x + f3.y);
        logit[t] = acc * msk[t] * 0.17677669529663687f;
    }

    float mx = logit[0];
    #pragma unroll
    for (int t = 1; t < 9; t++) mx = fmaxf(mx, logit[t]);
    float s = 0.f;
    #pragma unroll
    for (int t = 0; t < 9; t++) { logit[t] = __expf(logit[t] - mx); s += logit[t]; }
    const float inv = 1.f / s;
    #pragma unroll
    for (int t = 0; t < 9; t++) logit[t] *= inv * msk[t];

    float2 o[16];
    #pragma unroll
    for (int cp = 0; cp < 16; cp++) o[cp] = make_float2(0.f, 0.f);
    #pragma unroll
    for (int t = 0; t < 9; t++) {
        const float w = logit[t];
        #pragma unroll
        for (int g = 0; g < 4; g++) {
            float4 r = vf[gbase + (size_t)g * HWSZ + nn[t]];
            const __half2* h = (const __half2*)&r;
            #pragma unroll
            for (int u = 0; u < 4; u++) {
                float2 vv = __half22float2(h[u]);
                o[g*4+u].x += w * vv.x;
                o[g*4+u].y += w * vv.y;
            }
        }
    }

    float4* xp = (float4*)(xo + (size_t)(b * HWSZ + n) * CP2 + head * (HDIM/2));
    #pragma unroll
    for (int g = 0; g < 4; g++) {
        float4 r;
        __half2* h = (__half2*)&r;
        #pragma unroll
        for (int u = 0; u < 4; u++)
            h[u] = __floats2half2_rn(o[g*4+u].x, o[g*4+u].y);
        xp[g] = r;
    }
}

// =====================================================================
// LayerNorm over 256 channels: fp32 in (g_xp), fp16 out (g_ln).
// =====================================================================
__global__ void ln_kernel(const float* __restrict__ xp,
                          const float* __restrict__ w,
                          const float* __restrict__ bb,
                          __half2* __restrict__ out)
{
    const int warp = threadIdx.x >> 5;
    const int lane = threadIdx.x & 31;
    const int tok  = blockIdx.x * 8 + warp;
    const float* row = xp + (size_t)tok * CH;

    float4 v0 = *(const float4*)&row[lane * 8];
    float4 v1 = *(const float4*)&row[lane * 8 + 4];
    float va[8] = {v0.x, v0.y, v0.z, v0.w, v1.x, v1.y, v1.z, v1.w};

    float s = 0.f, sq = 0.f;
    #pragma unroll
    for (int u = 0; u < 8; u++) { s += va[u]; sq += va[u] * va[u]; }
    #pragma unroll
    for (int o = 16; o; o >>= 1) {
        s  += __shfl_xor_sync(0xffffffffu, s,  o);
        sq += __shfl_xor_sync(0xffffffffu, sq, o);
    }
    const float mean = s * (1.f / 256.f);
    const float var  = sq * (1.f / 256.f) - mean * mean;
    const float inv  = rsqrtf(var + 1e-5f);

    __half2* orow = out + (size_t)tok * CP2 + lane * 4;
    #pragma unroll
    for (int j = 0; j < 4; j++) {
        int ch = lane * 8 + j * 2;
        float a0 = (va[j*2]   - mean) * inv * w[ch]     + bb[ch];
        float a1 = (va[j*2+1] - mean) * inv * w[ch + 1] + bb[ch + 1];
        orow[j] = __floats2half2_rn(a0, a1);
    }
}

// =====================================================================
extern "C" void kernel_launch(void* const* d_in, const int* in_sizes, int n_in,
                              void* d_out, int out_size)
{
    const float* sub    = (const float*)d_in[0];
    const float* ori    = (const float*)d_in[1];
    const float* wq     = (const float*)d_in[2];
    const float* wk     = (const float*)d_in[3];
    const float* wv     = (const float*)d_in[4];
    const float* proj_w = (const float*)d_in[5];
    const float* proj_b = (const float*)d_in[6];
    const float* ln_w   = (const float*)d_in[7];
    const float* ln_b   = (const float*)d_in[8];
    const float* fc1_w  = (const float*)d_in[9];
    const float* fc1_b  = (const float*)d_in[10];
    const float* fc2_w  = (const float*)d_in[11];
    const float* fc2_b  = (const float*)d_in[12];
    float* out = (float*)d_out;

    __half *p_ts, *p_to, *p_ln, *p_h, *p_wq, *p_wkv, *p_wp, *p_w1, *p_w2;
    __half2 *p_q, *p_k, *p_v, *p_x;
    float *p_xp;
    cudaGetSymbolAddress((void**)&p_ts,  g_ts);
    cudaGetSymbolAddress((void**)&p_to,  g_to);
    cudaGetSymbolAddress((void**)&p_q,   g_q);
    cudaGetSymbolAddress((void**)&p_k,   g_k);
    cudaGetSymbolAddress((void**)&p_v,   g_v);
    cudaGetSymbolAddress((void**)&p_x,   g_x);
    cudaGetSymbolAddress((void**)&p_xp,  g_xp);
    cudaGetSymbolAddress((void**)&p_ln,  g_ln);
    cudaGetSymbolAddress((void**)&p_h,   g_h);
    cudaGetSymbolAddress((void**)&p_wq,  g_wq);
    cudaGetSymbolAddress((void**)&p_wkv, g_wkv);
    cudaGetSymbolAddress((void**)&p_wp,  g_wp);
    cudaGetSymbolAddress((void**)&p_w1,  g_w1);
    cudaGetSymbolAddress((void**)&p_w2,  g_w2);

    cudaFuncSetAttribute(gemm_h<6, CH >, cudaFuncAttributeMaxDynamicSharedMemorySize, SMEM_SZ);
    cudaFuncSetAttribute(gemm_h<0, CH >, cudaFuncAttributeMaxDynamicSharedMemorySize, SMEM_SZ);
    cudaFuncSetAttribute(gemm_h<1, CH >, cudaFuncAttributeMaxDynamicSharedMemorySize, SMEM_SZ);
    cudaFuncSetAttribute(gemm_h<2, HID>, cudaFuncAttributeMaxDynamicSharedMemorySize, SMEM_SZ);

    // 0: fused prologue (transposes + all weight conversions)
    dim3 gpre(HWSZ / 32, CH / 32, 19);   // z 0..15 transpose, 16..18 cvt
    dim3 bpre(32, 8);
    prep_all<<<gpre, bpre>>>(sub, ori, p_ts, p_to,
                             wq, wk, wv, proj_w, fc1_w, fc2_w,
                             p_wq, p_wkv, p_wp, p_w1, p_w2);

    // 1: combined q + kv GEMM (bx<2: q; bx>=2: k|v), grouped-channel out
    dim3 gqkv(6, NTOK / 128);
    gemm_h<6, CH><<<gqkv, 256, SMEM_SZ>>>(p_ts, p_wq, nullptr, p_q, p_k,
                                          p_to, p_wkv, p_v);

    // 2: attention -> g_x [tok][256] fp16
    dim3 ga(HWSZ / 128, NHEAD, BATCH);
    attn_kernel<<<ga, 128>>>((const float4*)p_q, (const float4*)p_k,
                             (const float4*)p_v, p_x);

    // 3: proj + bias -> g_xp fp32
    dim3 gp(CH / 128, NTOK / 128);
    gemm_h<0, CH><<<gp, 256, SMEM_SZ>>>((const __half*)p_x, p_wp, proj_b, p_xp,
                                        nullptr, nullptr, nullptr, nullptr);

    // 4: layernorm -> g_ln fp16
    ln_kernel<<<NTOK / 8, 256>>>(p_xp, ln_w, ln_b, (__half2*)p_ln);

    // 5: fc1 + bias + GELU -> g_h fp16
    dim3 g1(HID / 128, NTOK / 128);
    gemm_h<1, CH><<<g1, 256, SMEM_SZ>>>(p_ln, p_w1, fc1_b, p_h,
                                        nullptr, nullptr, nullptr, nullptr);

    // 6: fc2 + bias + residual, transposed fp32 store -> d_out [B][C][H][W]
    dim3 g2(CH / 128, NTOK / 128);
    gemm_h<2, HID><<<g2, 256, SMEM_SZ>>>(p_h, p_w2, fc2_b, out, p_xp,
                                         nullptr, nullptr, nullptr);
}

// round 16
// speedup vs baseline: 1.3336x; 1.0469x over previous
#include <cuda_runtime.h>
#include <cuda_fp16.h>
#include <math.h>
#include <stdint.h>

// ---------------- problem constants ----------------
#define BATCH   8
#define CH      256
#define HH      64
#define WW      64
#define HWSZ    (HH*WW)          // 4096
#define NTOK    (BATCH*HWSZ)     // 32768
#define HID     1024
#define NHEAD   8
#define HDIM    32
#define CP2     (CH/2)           // 128 channel pairs
#define NGRP    32               // channel groups of 8 halves (16B)

// ---------------- scratch ----------------
__device__ __half  g_ts[NTOK*CH];        // sub transposed [tok][c]
__device__ __half  g_to[NTOK*CH];        // ori transposed [tok][c]
__device__ __half2 g_q [BATCH*NGRP*HWSZ*4];  // grouped [b][grp][hw][8]
__device__ __half2 g_k [BATCH*NGRP*HWSZ*4];
__device__ __half2 g_v [BATCH*NGRP*HWSZ*4];
__device__ __half2 g_x [NTOK*CP2];       // attention out, [tok][c] rows
__device__ float   g_xp[NTOK*CH];        // proj out fp32 (residual)
__device__ __half  g_ln[NTOK*CH];        // layernorm out
__device__ __half  g_h [NTOK*HID];       // mlp hidden
__device__ __half  g_wq [CH*CH];         // fp16 weights
__device__ __half  g_wkv[2*CH*CH];       // wk rows 0..255 | wv rows 256..511
__device__ __half  g_wp [CH*CH];
__device__ __half  g_w1 [HID*CH];
__device__ __half  g_w2 [CH*HID];

// ---------------- helpers ----------------
__device__ __forceinline__ uint32_t smem_u32(const void* p) {
    uint32_t a;
    asm("{ .reg .u64 t; cvta.to.shared.u64 t, %1; cvt.u32.u64 %0, t; }"
        : "=r"(a) : "l"(p));
    return a;
}
__device__ __forceinline__ void cp16(uint32_t s, const void* g) {
    asm volatile("cp.async.cg.shared.global [%0], [%1], 16;" :: "r"(s), "l"(g));
}
#define CP_COMMIT() asm volatile("cp.async.commit_group;" ::: "memory")
#define CP_WAIT1()  asm volatile("cp.async.wait_group 1;" ::: "memory")

__device__ __forceinline__ void ldsm_x4(uint32_t r[4], uint32_t addr) {
    asm volatile("ldmatrix.sync.aligned.m8n8.x4.shared.b16 {%0,%1,%2,%3}, [%4];"
        : "=r"(r[0]), "=r"(r[1]), "=r"(r[2]), "=r"(r[3]) : "r"(addr));
}
__device__ __forceinline__ void mma_f16(float c[4], const uint32_t a[4],
                                        uint32_t b0, uint32_t b1) {
    asm volatile(
        "mma.sync.aligned.m16n8k16.row.col.f32.f16.f16.f32 "
        "{%0,%1,%2,%3}, {%4,%5,%6,%7}, {%8,%9}, {%0,%1,%2,%3};\n"
        : "+f"(c[0]), "+f"(c[1]), "+f"(c[2]), "+f"(c[3])
        : "r"(a[0]), "r"(a[1]), "r"(a[2]), "r"(a[3]), "r"(b0), "r"(b1));
}

// =====================================================================
// fp16 NT GEMM. Warp tile 32x64 throughout (proven).
// MODE 6: qkv, CTA 128x128, 3-stage, single sync. Grouped-channel stores.
// MODE 1: fc1, CTA 128x128, 3-stage. +bias, GELU, half [m][HID]
// MODE 2: fc2, CTA 128x128, 3-stage. +bias +resid, transposed fp32 store
// MODE 7: proj+LN, CTA 64x256 (8 warps = 2m x 4n), 2-stage double-sync.
//         +bias -> xp fp32 (out1) AND fused LayerNorm -> ln half (aux).
// =====================================================================
#define STAGE_B 32768          // modes 6/1/2: 16KB A + 16KB B
#define SMEM_SZ (3*STAGE_B)
#define STAGE_B7 40960         // mode 7: 8KB A + 32KB B
#define SMEM_SZ7 (2*STAGE_B7)

template<int MODE, int KDIM>
__global__ __launch_bounds__(256, 2)
void gemm_h(const __half* __restrict__ A, const __half* __restrict__ Wt,
            const float* __restrict__ bias, void* __restrict__ out1,
            void* __restrict__ aux,
            const __half* __restrict__ A2, const __half* __restrict__ W2,
            void* __restrict__ out2,
            const float* __restrict__ lnw, const float* __restrict__ lnb)
{
    extern __shared__ __align__(128) char smem[];
    const uint32_t sb = smem_u32(smem);

    const int tid  = threadIdx.x;
    const int lane = tid & 31;
    const int wid  = tid >> 5;
    const int wm   = (MODE == 7) ? (wid & 1) : (wid & 3);
    const int wn   = (MODE == 7) ? (wid >> 1) : (wid >> 2);
    const int lq   = lane >> 2;
    const int lr   = lane & 3;

    const __half* Ap;
    const __half* Wp;
    int nT;
    bool isq = true;
    if (MODE == 6) {
        isq = (blockIdx.x < 2);
        if (isq) { Ap = A;  Wp = Wt; nT = blockIdx.x * 128; }
        else     { Ap = A2; Wp = W2; nT = (blockIdx.x - 2) * 128; }
    } else {
        Ap = A; Wp = Wt; nT = blockIdx.x * ((MODE == 7) ? 256 : 128);
    }
    const int MTILE = (MODE == 7) ? 64 : 128;
    const int mT = blockIdx.y * MTILE;
    const int NCH = KDIM / 64;
    const uint32_t boff = (MODE == 7) ? 8192u : 16384u;

    const int arow  = wm * 32 + (lane & 15);
    const int aqsel = lane >> 4;
    const uint32_t abase0 = (uint32_t)arow * 128;
    const uint32_t abase1 = (uint32_t)(arow + 16) * 128;
    const int axor = arow & 7;
    const int brow  = wn * 64 + (lane & 15);
    const int bqsel = lane >> 4;

    float acc[2][8][4];
    #pragma unroll
    for (int i = 0; i < 2; i++)
        #pragma unroll
        for (int j = 0; j < 8; j++)
            #pragma unroll
            for (int u = 0; u < 4; u++) acc[i][j][u] = 0.f;

    auto load_stage = [&](int s, int kt) {
        const uint32_t ab = sb + s * ((MODE == 7) ? STAGE_B7 : STAGE_B);
        const uint32_t bbm = ab + boff;
        if (MODE == 7) {
            #pragma unroll
            for (int j = 0; j < 2; j++) {          // A: 64 rows x 8 q16
                int c = tid + j * 256;
                int row = c >> 3, q = c & 7;
                uint32_t off = (uint32_t)row * 128 + (uint32_t)((q ^ (row & 7)) * 16);
                cp16(ab + off, Ap + (size_t)(mT + row) * KDIM + kt + q * 8);
            }
            #pragma unroll
            for (int j = 0; j < 8; j++) {          // B: 256 rows x 8 q16
                int c = tid + j * 256;
                int row = c >> 3, q = c & 7;
                uint32_t off = (uint32_t)row * 128 + (uint32_t)((q ^ (row & 7)) * 16);
                cp16(bbm + off, Wp + (size_t)(nT + row) * KDIM + kt + q * 8);
            }
        } else {
            #pragma unroll
            for (int j = 0; j < 4; j++) {
                int c = tid + j * 256;
                int row = c >> 3, q = c & 7;
                uint32_t off = (uint32_t)row * 128 + (uint32_t)((q ^ (row & 7)) * 16);
                cp16(ab  + off, Ap + (size_t)(mT + row) * KDIM + kt + q * 8);
                cp16(bbm + off, Wp + (size_t)(nT + row) * KDIM + kt + q * 8);
            }
        }
    };

    auto compute_chunk = [&](uint32_t ab) {
        const uint32_t bbm = ab + boff;
        #pragma unroll
        for (int ks = 0; ks < 4; ks++) {
            const int q0 = ks * 2;
            uint32_t af[2][4];
            {
                const int qa = q0 + aqsel;
                ldsm_x4(af[0], ab + abase0 + (uint32_t)((qa ^ axor) * 16));
                ldsm_x4(af[1], ab + abase1 + (uint32_t)((qa ^ axor) * 16));
            }
            #pragma unroll
            for (int nt2 = 0; nt2 < 4; nt2++) {
                const int row = brow + nt2 * 16;
                const int qb = q0 + bqsel;
                uint32_t bf[4];
                ldsm_x4(bf, bbm + (uint32_t)row * 128 + (uint32_t)((qb ^ (row & 7)) * 16));
                mma_f16(acc[0][nt2*2  ], af[0], bf[0], bf[2]);
                mma_f16(acc[0][nt2*2+1], af[0], bf[1], bf[3]);
                mma_f16(acc[1][nt2*2  ], af[1], bf[0], bf[2]);
                mma_f16(acc[1][nt2*2+1], af[1], bf[1], bf[3]);
            }
        }
    };

    if (MODE == 7) {
        // 2-stage, double-sync pipeline
        load_stage(0, 0);  CP_COMMIT();
        load_stage(1, 64); CP_COMMIT();
        for (int it = 0; it < NCH; it++) {
            CP_WAIT1();
            __syncthreads();
            compute_chunk(sb + (it & 1) * STAGE_B7);
            __syncthreads();
            if (it + 2 < NCH) load_stage(it & 1, (it + 2) * 64);
            CP_COMMIT();
        }
    } else {
        // 3-stage, single-sync pipeline
        load_stage(0, 0);  CP_COMMIT();
        if (NCH > 1) load_stage(1, 64);
        CP_COMMIT();
        for (int it = 0; it < NCH; it++) {
            CP_WAIT1();
            __syncthreads();
            if (it + 2 < NCH) load_stage((it + 2) % 3, (it + 2) * 64);
            CP_COMMIT();
            compute_chunk(sb + (it % 3) * STAGE_B);
        }
    }

    // ---------------- epilogue ----------------
    if (MODE == 7) {
        __shared__ float s_sum[4][64];
        __shared__ float s_sq [4][64];
        float* xp = (float*)out1;
        __half2* lo = (__half2*)aux;

        float ps[4] = {0, 0, 0, 0}, pq[4] = {0, 0, 0, 0};
        // bias add + xp store + partials
        #pragma unroll
        for (int mt = 0; mt < 2; mt++) {
            #pragma unroll
            for (int idx = 0; idx < 8; idx++) {
                const int nt2 = idx >> 1, tt = idx & 1;
                const int m0 = mT + wm * 32 + mt * 16 + lq;
                const int n0 = wn * 64 + nt2 * 16 + tt * 8 + (lr << 1);
                float* cc = acc[mt][idx];
                float2 bv = *(const float2*)&bias[n0];
                cc[0] += bv.x; cc[1] += bv.y; cc[2] += bv.x; cc[3] += bv.y;
                *(float2*)&xp[(size_t)m0 * CH + n0]       = make_float2(cc[0], cc[1]);
                *(float2*)&xp[(size_t)(m0 + 8) * CH + n0] = make_float2(cc[2], cc[3]);
                ps[mt*2  ] += cc[0] + cc[1];
                pq[mt*2  ] += cc[0]*cc[0] + cc[1]*cc[1];
                ps[mt*2+1] += cc[2] + cc[3];
                pq[mt*2+1] += cc[2]*cc[2] + cc[3]*cc[3];
            }
        }
        // quad reduce over lr
        #pragma unroll
        for (int o = 1; o <= 2; o <<= 1)
            #pragma unroll
            for (int r = 0; r < 4; r++) {
                ps[r] += __shfl_xor_sync(0xffffffffu, ps[r], o);
                pq[r] += __shfl_xor_sync(0xffffffffu, pq[r], o);
            }
        if (lr == 0) {
            #pragma unroll
            for (int r = 0; r < 4; r++) {
                const int rloc = wm * 32 + (r >> 1) * 16 + (r & 1) * 8 + lq;
                s_sum[wn][rloc] = ps[r];
                s_sq [wn][rloc] = pq[r];
            }
        }
        __syncthreads();
        float mean[4], inv[4];
        #pragma unroll
        for (int r = 0; r < 4; r++) {
            const int rloc = wm * 32 + (r >> 1) * 16 + (r & 1) * 8 + lq;
            float s = s_sum[0][rloc] + s_sum[1][rloc] + s_sum[2][rloc] + s_sum[3][rloc];
            float q = s_sq [0][rloc] + s_sq [1][rloc] + s_sq [2][rloc] + s_sq [3][rloc];
            mean[r] = s * (1.f / 256.f);
            float var = q * (1.f / 256.f) - mean[r] * mean[r];
            inv[r] = rsqrtf(var + 1e-5f);
        }
        #pragma unroll
        for (int mt = 0; mt < 2; mt++) {
            #pragma unroll
            for (int idx = 0; idx < 8; idx++) {
                const int nt2 = idx >> 1, tt = idx & 1;
                const int m0 = mT + wm * 32 + mt * 16 + lq;
                const int n0 = wn * 64 + nt2 * 16 + tt * 8 + (lr << 1);
                const float* cc = acc[mt][idx];
                float2 lw = *(const float2*)&lnw[n0];
                float2 lb = *(const float2*)&lnb[n0];
                const int r0 = mt * 2, r1 = mt * 2 + 1;
                lo[(size_t)m0 * CP2 + (n0 >> 1)] = __floats2half2_rn(
                    (cc[0] - mean[r0]) * inv[r0] * lw.x + lb.x,
                    (cc[1] - mean[r0]) * inv[r0] * lw.y + lb.y);
                lo[(size_t)(m0 + 8) * CP2 + (n0 >> 1)] = __floats2half2_rn(
                    (cc[2] - mean[r1]) * inv[r1] * lw.x + lb.x,
                    (cc[3] - mean[r1]) * inv[r1] * lw.y + lb.y);
            }
        }
        return;
    }

    #pragma unroll
    for (int mt = 0; mt < 2; mt++) {
        #pragma unroll
        for (int idx = 0; idx < 8; idx++) {
            const int nt2 = idx >> 1, tt = idx & 1;
            const int m0 = mT + wm * 32 + mt * 16 + lq;
            const int n0 = nT + wn * 64 + nt2 * 16 + tt * 8 + (lr << 1);
            const float* cc = acc[mt][idx];

            if (MODE == 6) {
                const int bi = m0 >> 12;
                const int hw = m0 & 4095;
                __half2* dst = isq ? (__half2*)out1
                                   : ((n0 < CH) ? (__half2*)aux : (__half2*)out2);
                const int ch  = n0 & (CH - 1);
                const int grp = ch >> 3;
                const int wi  = (ch & 7) >> 1;
                __half2* p = dst + ((((size_t)bi * NGRP + grp) * HWSZ + hw) << 2) + wi;
                p[0]  = __floats2half2_rn(cc[0], cc[1]);
                p[32] = __floats2half2_rn(cc[2], cc[3]);
            } else if (MODE == 1) {
                __half* o = (__half*)out1;
                float2 bv = *(const float2*)&bias[n0];
                float v[4] = {cc[0] + bv.x, cc[1] + bv.y, cc[2] + bv.x, cc[3] + bv.y};
                #pragma unroll
                for (int u = 0; u < 4; u++)
                    v[u] = 0.5f * v[u] * (1.f + erff(v[u] * 0.70710678118654752f));
                *(__half2*)&o[(size_t)m0 * HID + n0]       = __floats2half2_rn(v[0], v[1]);
                *(__half2*)&o[(size_t)(m0 + 8) * HID + n0] = __floats2half2_rn(v[2], v[3]);
            } else {
                float* o = (float*)out1;
                const float* resid = (const float*)aux;
                float2 bv = *(const float2*)&bias[n0];
                float2 r0 = *(const float2*)&resid[(size_t)m0 * CH + n0];
                float2 r1 = *(const float2*)&resid[(size_t)(m0 + 8) * CH + n0];
                const int bi = m0 >> 12;
                const int hw = m0 & 4095;
                float* p = o + (size_t)bi * CH * HWSZ;
                p[(size_t)(n0    ) * HWSZ + hw    ] = cc[0] + bv.x + r0.x;
                p[(size_t)(n0 + 1) * HWSZ + hw    ] = cc[1] + bv.y + r0.y;
                p[(size_t)(n0    ) * HWSZ + hw + 8] = cc[2] + bv.x + r1.x;
                p[(size_t)(n0 + 1) * HWSZ + hw + 8] = cc[3] + bv.y + r1.y;
            }
        }
    }
}

// =====================================================================
// Fused prologue: z 0..15 transpose (+fp16 cvt); z 16..18 weight cvt.
// =====================================================================
__global__ void prep_all(const float* __restrict__ sub, const float* __restrict__ ori,
                         __half* __restrict__ ts, __half* __restrict__ to,
                         const float* __restrict__ wq, const float* __restrict__ wk,
                         const float* __restrict__ wv, const float* __restrict__ wp,
                         const float* __restrict__ w1, const float* __restrict__ w2,
                         __half* __restrict__ owq, __half* __restrict__ owkv,
                         __half* __restrict__ owp, __half* __restrict__ ow1,
                         __half* __restrict__ ow2)
{
    const int z = blockIdx.z;
    if (z < 16) {
        __shared__ float t[32][33];
        const int b  = z & 7;
        const float* in = (z < 8) ? sub : ori;
        __half* out     = (z < 8) ? ts  : to;
        const int p0 = blockIdx.x * 32;
        const int c0 = blockIdx.y * 32;
        const int tx = threadIdx.x, ty = threadIdx.y;
        const float* ib = in + (size_t)b * CH * HWSZ;
        __half* ob = out + (size_t)b * HWSZ * CH;
        #pragma unroll
        for (int i = 0; i < 4; i++)
            t[ty + 8*i][tx] = ib[(size_t)(c0 + ty + 8*i) * HWSZ + p0 + tx];
        __syncthreads();
        #pragma unroll
        for (int i = 0; i < 4; i++)
            ob[(size_t)(p0 + ty + 8*i) * CH + c0 + tx] = __float2half_rn(t[tx][ty + 8*i]);
    } else {
        const int tid = threadIdx.y * 32 + threadIdx.x;
        const int slot = ((z - 16) * gridDim.y + blockIdx.y) * gridDim.x + blockIdx.x;
        const int i = slot * 256 + tid;
        const int S = CH * CH;
        if (i >= 12 * S) return;
        if      (i <     S) owq [i      ] = __float2half_rn(wq[i]);
        else if (i < 2 * S) owkv[i - S  ] = __float2half_rn(wk[i - S]);
        else if (i < 3 * S) owkv[i - S  ] = __float2half_rn(wv[i - 2*S]);
        else if (i < 4 * S) owp [i - 3*S] = __float2half_rn(wp[i - 3*S]);
        else if (i < 8 * S) ow1 [i - 4*S] = __float2half_rn(w1[i - 4*S]);
        else                ow2 [i - 8*S] = __float2half_rn(w2[i - 8*S]);
    }
}

// =====================================================================
// Dilated 3x3 local attention, grouped q/k/v, HFMA2 logits (proven).
// =====================================================================
__global__ __launch_bounds__(128)
void attn_kernel(const float4* __restrict__ qf,
                 const float4* __restrict__ kf,
                 const float4* __restrict__ vf,
                 __half2* __restrict__ xo)
{
    const int b    = blockIdx.z;
    const int head = blockIdx.y;
    const int n    = blockIdx.x * 128 + threadIdx.x;
    const int py   = n >> 6;
    const int px   = n & 63;
    const int dil  = (head >> 1) + 1;

    const size_t gbase = ((size_t)b * NGRP + head * 4) * HWSZ;

    __half2 qh[16];
    #pragma unroll
    for (int g = 0; g < 4; g++) {
        float4 r = qf[gbase + (size_t)g * HWSZ + n];
        const __half2* h = (const __half2*)&r;
        qh[g*4+0] = h[0]; qh[g*4+1] = h[1]; qh[g*4+2] = h[2]; qh[g*4+3] = h[3];
    }

    int nn[9];
    float msk[9];
    #pragma unroll
    for (int t = 0; t < 9; t++) {
        int yy = py + (t / 3 - 1) * dil;
        int xx = px + (t % 3 - 1) * dil;
        const bool in = (yy >= 0 && yy < HH && xx >= 0 && xx < WW);
        nn[t] = in ? (yy * WW + xx) : n;
        msk[t] = in ? 1.f : 0.f;
    }

    const __half2 hz = __floats2half2_rn(0.f, 0.f);
    float logit[9];
    #pragma unroll
    for (int t = 0; t < 9; t++) {
        __half2 pa[4] = {hz, hz, hz, hz};
        #pragma unroll
        for (int g = 0; g < 4; g++) {
            float4 r = kf[gbase + (size_t)g * HWSZ + nn[t]];
            const __half2* h = (const __half2*)&r;
            #pragma unroll
            for (int u = 0; u < 4; u++)
                pa[u] = __hfma2(qh[g*4+u], h[u], pa[u]);
        }
        float2 f0 = __half22float2(pa[0]);
        float2 f1 = __half22float2(pa[1]);
        float2 f2 = __half22float2(pa[2]);
        float2 f3 = __half22float2(pa[3]);
        float acc = (f0.x + f0.y) + (f1.x + f1.y) + (f2.x + f2.y) + (f3.x + f3.y);
        logit[t] = acc * msk[t] * 0.17677669529663687f;
    }

    float mx = logit[0];
    #pragma unroll
    for (int t = 1; t < 9; t++) mx = fmaxf(mx, logit[t]);
    float s = 0.f;
    #pragma unroll
    for (int t = 0; t < 9; t++) { logit[t] = __expf(logit[t] - mx); s += logit[t]; }
    const float inv = 1.f / s;
    #pragma unroll
    for (int t = 0; t < 9; t++) logit[t] *= inv * msk[t];

    float2 o[16];
    #pragma unroll
    for (int cp = 0; cp < 16; cp++) o[cp] = make_float2(0.f, 0.f);
    #pragma unroll
    for (int t = 0; t < 9; t++) {
        const float w = logit[t];
        #pragma unroll
        for (int g = 0; g < 4; g++) {
            float4 r = vf[gbase + (size_t)g * HWSZ + nn[t]];
            const __half2* h = (const __half2*)&r;
            #pragma unroll
            for (int u = 0; u < 4; u++) {
                float2 vv = __half22float2(h[u]);
                o[g*4+u].x += w * vv.x;
                o[g*4+u].y += w * vv.y;
            }
        }
    }

    float4* xp = (float4*)(xo + (size_t)(b * HWSZ + n) * CP2 + head * (HDIM/2));
    #pragma unroll
    for (int g = 0; g < 4; g++) {
        float4 r;
        __half2* h = (__half2*)&r;
        #pragma unroll
        for (int u = 0; u < 4; u++)
            h[u] = __floats2half2_rn(o[g*4+u].x, o[g*4+u].y);
        xp[g] = r;
    }
}

// =====================================================================
extern "C" void kernel_launch(void* const* d_in, const int* in_sizes, int n_in,
                              void* d_out, int out_size)
{
    const float* sub    = (const float*)d_in[0];
    const float* ori    = (const float*)d_in[1];
    const float* wq     = (const float*)d_in[2];
    const float* wk     = (const float*)d_in[3];
    const float* wv     = (const float*)d_in[4];
    const float* proj_w = (const float*)d_in[5];
    const float* proj_b = (const float*)d_in[6];
    const float* ln_w   = (const float*)d_in[7];
    const float* ln_b   = (const float*)d_in[8];
    const float* fc1_w  = (const float*)d_in[9];
    const float* fc1_b  = (const float*)d_in[10];
    const float* fc2_w  = (const float*)d_in[11];
    const float* fc2_b  = (const float*)d_in[12];
    float* out = (float*)d_out;

    __half *p_ts, *p_to, *p_ln, *p_h, *p_wq, *p_wkv, *p_wp, *p_w1, *p_w2;
    __half2 *p_q, *p_k, *p_v, *p_x;
    float *p_xp;
    cudaGetSymbolAddress((void**)&p_ts,  g_ts);
    cudaGetSymbolAddress((void**)&p_to,  g_to);
    cudaGetSymbolAddress((void**)&p_q,   g_q);
    cudaGetSymbolAddress((void**)&p_k,   g_k);
    cudaGetSymbolAddress((void**)&p_v,   g_v);
    cudaGetSymbolAddress((void**)&p_x,   g_x);
    cudaGetSymbolAddress((void**)&p_xp,  g_xp);
    cudaGetSymbolAddress((void**)&p_ln,  g_ln);
    cudaGetSymbolAddress((void**)&p_h,   g_h);
    cudaGetSymbolAddress((void**)&p_wq,  g_wq);
    cudaGetSymbolAddress((void**)&p_wkv, g_wkv);
    cudaGetSymbolAddress((void**)&p_wp,  g_wp);
    cudaGetSymbolAddress((void**)&p_w1,  g_w1);
    cudaGetSymbolAddress((void**)&p_w2,  g_w2);

    cudaFuncSetAttribute(gemm_h<6, CH >, cudaFuncAttributeMaxDynamicSharedMemorySize, SMEM_SZ);
    cudaFuncSetAttribute(gemm_h<7, CH >, cudaFuncAttributeMaxDynamicSharedMemorySize, SMEM_SZ7);
    cudaFuncSetAttribute(gemm_h<1, CH >, cudaFuncAttributeMaxDynamicSharedMemorySize, SMEM_SZ);
    cudaFuncSetAttribute(gemm_h<2, HID>, cudaFuncAttributeMaxDynamicSharedMemorySize, SMEM_SZ);

    // 0: fused prologue (transposes + all weight conversions)
    dim3 gpre(HWSZ / 32, CH / 32, 19);
    dim3 bpre(32, 8);
    prep_all<<<gpre, bpre>>>(sub, ori, p_ts, p_to,
                             wq, wk, wv, proj_w, fc1_w, fc2_w,
                             p_wq, p_wkv, p_wp, p_w1, p_w2);

    // 1: combined q + kv GEMM (bx<2: q; bx>=2: k|v), grouped-channel out
    dim3 gqkv(6, NTOK / 128);
    gemm_h<6, CH><<<gqkv, 256, SMEM_SZ>>>(p_ts, p_wq, nullptr, p_q, p_k,
                                          p_to, p_wkv, p_v, nullptr, nullptr);

    // 2: attention -> g_x [tok][256] fp16
    dim3 ga(HWSZ / 128, NHEAD, BATCH);
    attn_kernel<<<ga, 128>>>((const float4*)p_q, (const float4*)p_k,
                             (const float4*)p_v, p_x);

    // 3: proj + bias + fused LayerNorm -> g_xp (fp32), g_ln (fp16)
    dim3 gp(1, NTOK / 64);
    gemm_h<7, CH><<<gp, 256, SMEM_SZ7>>>((const __half*)p_x, p_wp, proj_b, p_xp,
                                         p_ln, nullptr, nullptr, nullptr,
                                         ln_w, ln_b);

    // 4: fc1 + bias + GELU -> g_h fp16
    dim3 g1(HID / 128, NTOK / 128);
    gemm_h<1, CH><<<g1, 256, SMEM_SZ>>>(p_ln, p_w1, fc1_b, p_h,
                                        nullptr, nullptr, nullptr, nullptr,
                                        nullptr, nullptr);

    // 5: fc2 + bias + residual, transposed fp32 store -> d_out [B][C][H][W]
    dim3 g2(CH / 128, NTOK / 128);
    gemm_h<2, HID><<<g2, 256, SMEM_SZ>>>(p_h, p_w2, fc2_b, out, p_xp,
                                         nullptr, nullptr, nullptr,
                                         nullptr, nullptr);
}